// round 1
// baseline (speedup 1.0000x reference)
#include <cuda_runtime.h>
#include <cuda_bf16.h>
#include <math.h>

// Problem constants
constexpr int B = 2, T = 2048, D = 1024, H = 16, HD = 32, INNER = 512, FF = 4096;
constexpr int M = B * T;              // 4096 rows
constexpr int NPROJ = D + 3 * INNER;  // 2560
constexpr int KT = 3, KP = 15;
constexpr int CHUNK = 64, NC = T / CHUNK;   // 32 chunks
constexpr int STATE_STRIDE = HD * HD + HD;  // 1056 floats per (bh, chunk)

// Scratch (allocations are forbidden -> __device__ globals)
__device__ float g_normed[M * D];
__device__ float g_proj[M * NPROJ];
__device__ float g_attn[M * INNER];
__device__ float g_cat[M * 3 * D];
__device__ float g_mixed[M * D];
__device__ float g_out1[M * D];
__device__ float g_h[M * D];
__device__ float g_ffn1[(size_t)M * FF];
__device__ float g_state[B * H * NC * STATE_STRIDE];

// ---------------------------------------------------------------------------
// LayerNorm: one block per row (D=1024), 256 threads, float4 per thread.
// ---------------------------------------------------------------------------
__global__ void layernorm_kernel(const float* __restrict__ x,
                                 const float* __restrict__ g,
                                 const float* __restrict__ bta,
                                 float* __restrict__ y) {
    int row = blockIdx.x;
    int tid = threadIdx.x;
    float4 v = ((const float4*)(x + (size_t)row * D))[tid];
    float s = v.x + v.y + v.z + v.w;
    float sq = v.x * v.x + v.y * v.y + v.z * v.z + v.w * v.w;
    __shared__ float ss[256], sv[256];
    ss[tid] = s; sv[tid] = sq;
    __syncthreads();
    #pragma unroll
    for (int o = 128; o; o >>= 1) {
        if (tid < o) { ss[tid] += ss[tid + o]; sv[tid] += sv[tid + o]; }
        __syncthreads();
    }
    float mu = ss[0] * (1.0f / D);
    float var = sv[0] * (1.0f / D) - mu * mu;
    float rstd = rsqrtf(var + 1e-5f);
    int c = tid * 4;
    float4 gv = *(const float4*)(g + c);
    float4 bv = *(const float4*)(bta + c);
    float4 o;
    o.x = (v.x - mu) * rstd * gv.x + bv.x;
    o.y = (v.y - mu) * rstd * gv.y + bv.y;
    o.z = (v.z - mu) * rstd * gv.z + bv.z;
    o.w = (v.w - mu) * rstd * gv.w + bv.w;
    ((float4*)(y + (size_t)row * D))[tid] = o;
}

// ---------------------------------------------------------------------------
// Generic fp32 GEMM: C[M,N] = A[M,K] @ W[K,N] (+bias, epilogue).
// 128x128 tile, BK=8, 256 threads, 8x8 per thread.
// EPI 0: +bias ; EPI 1: gelu(acc+bias) ; EPI 2: (acc+bias+aux)*maskrow
// Requires M%128==0, N%128==0, K%8==0 (true for all call sites).
// ---------------------------------------------------------------------------
#define BM 128
#define BN 128
#define BK 8

template <int EPI>
__global__ void __launch_bounds__(256)
gemm_kernel(const float* __restrict__ A, int lda,
            const float* __restrict__ Bw, int ldb,
            float* __restrict__ C, int ldc,
            const float* __restrict__ bias,
            const float* __restrict__ aux, int ldaux,
            const float* __restrict__ mrow,
            int Mm, int Nn, int Kk) {
    __shared__ float As[BK][BM];
    __shared__ float Bs[BK][BN];
    int tid = threadIdx.x;
    int tx = tid % 16, ty = tid / 16;
    int m0 = blockIdx.y * BM, n0 = blockIdx.x * BN;

    int aRow = tid >> 1;           // 0..127
    int aCol = (tid & 1) * 4;      // 0 or 4
    int bRow = tid >> 5;           // 0..7
    int bCol = (tid & 31) * 4;     // 0..124

    float acc[8][8] = {};
    for (int k0 = 0; k0 < Kk; k0 += BK) {
        float4 av = *(const float4*)(A + (size_t)(m0 + aRow) * lda + k0 + aCol);
        As[aCol + 0][aRow] = av.x;
        As[aCol + 1][aRow] = av.y;
        As[aCol + 2][aRow] = av.z;
        As[aCol + 3][aRow] = av.w;
        float4 bv = *(const float4*)(Bw + (size_t)(k0 + bRow) * ldb + n0 + bCol);
        *(float4*)(&Bs[bRow][bCol]) = bv;
        __syncthreads();
        #pragma unroll
        for (int k = 0; k < BK; k++) {
            float ar[8], br[8];
            #pragma unroll
            for (int i = 0; i < 8; i++) ar[i] = As[k][ty * 8 + i];
            #pragma unroll
            for (int j = 0; j < 8; j++) br[j] = Bs[k][tx * 8 + j];
            #pragma unroll
            for (int i = 0; i < 8; i++)
                #pragma unroll
                for (int j = 0; j < 8; j++)
                    acc[i][j] += ar[i] * br[j];
        }
        __syncthreads();
    }
    #pragma unroll
    for (int i = 0; i < 8; i++) {
        int row = m0 + ty * 8 + i;
        float mval = 1.0f;
        if (EPI == 2) mval = mrow[row];
        #pragma unroll
        for (int j = 0; j < 8; j++) {
            int col = n0 + tx * 8 + j;
            float v = acc[i][j] + bias[col];
            if (EPI == 1) v = 0.5f * v * (1.0f + erff(v * 0.70710678118654752f));
            if (EPI == 2) v = (v + aux[(size_t)row * ldaux + col]) * mval;
            C[(size_t)row * ldc + col] = v;
        }
    }
}

// ---------------------------------------------------------------------------
// Causal depthwise conv over time (cross-correlation, left-pad k-1).
// y[b,t,d] = bias[d] + sum_j w[d,0,j] * x[b, t-(k-1)+j, d]
// Output written into g_cat at a column offset (row stride 3*D).
// ---------------------------------------------------------------------------
template <int KW>
__global__ void dwconv_kernel(const float* __restrict__ x,
                              const float* __restrict__ w,
                              const float* __restrict__ bias,
                              float* __restrict__ y /* pre-offset, stride 3D */) {
    int idx = blockIdx.x * blockDim.x + threadIdx.x;  // over M*D
    int d = idx & (D - 1);
    int bt = idx >> 10;
    int t = bt & (T - 1);
    float acc = bias[d];
    #pragma unroll
    for (int j = 0; j < KW; j++) {
        int tt = t - (KW - 1) + j;
        if (tt >= 0)
            acc += w[d * KW + j] * x[((size_t)(bt - (KW - 1) + j)) * D + d];
    }
    y[(size_t)bt * (3 * D) + d] = acc;
}

// ---------------------------------------------------------------------------
// Linear attention, chunked scan. Block = (32,32): thread (d,e) owns S[d][e].
// Pass 1: per (b,h,chunk) local sums of k (x) v and k.
// Pass 2: prefix from pass-1 states, then inclusive sequential scan in-chunk.
// ---------------------------------------------------------------------------
__device__ __forceinline__ float elu1(float x) {
    return x > 0.0f ? x + 1.0f : expf(x);
}

__global__ void __launch_bounds__(1024)
attn_pass1(const float* __restrict__ proj, const float* __restrict__ mask,
           float* __restrict__ state) {
    int bh = blockIdx.x / NC, c = blockIdx.x % NC;
    int b = bh / H, h = bh % H;
    int d = threadIdx.x, e = threadIdx.y;
    int tid = e * 32 + d;
    __shared__ float ks[CHUNK][32];
    __shared__ float vs[CHUNK][32];
    int t0 = c * CHUNK;
    for (int i = tid; i < CHUNK * 32; i += 1024) {
        int t = i >> 5, dd = i & 31;
        int rowg = b * T + t0 + t;
        size_t base = (size_t)rowg * NPROJ;
        float m = mask[rowg];
        float kv = proj[base + 1536 + h * 32 + dd];
        ks[t][dd] = elu1(kv) * m;
        vs[t][dd] = proj[base + 2048 + h * 32 + dd] * m;
    }
    __syncthreads();
    float S = 0.0f, kp = 0.0f;
    #pragma unroll 4
    for (int t = 0; t < CHUNK; t++) {
        float kd = ks[t][d];
        S += kd * vs[t][e];
        kp += kd;
    }
    float* st = state + (size_t)blockIdx.x * STATE_STRIDE;
    st[e * 32 + d] = S;
    if (e == 0) st[1024 + d] = kp;
}

__global__ void __launch_bounds__(1024)
attn_pass2(const float* __restrict__ proj, const float* __restrict__ mask,
           const float* __restrict__ state, float* __restrict__ outa) {
    int bh = blockIdx.x / NC, c = blockIdx.x % NC;
    int b = bh / H, h = bh % H;
    int d = threadIdx.x, e = threadIdx.y;
    int tid = e * 32 + d;
    __shared__ float qs[CHUNK][32];
    __shared__ float ks[CHUNK][32];
    __shared__ float vs[CHUNK][32];
    __shared__ float ms[CHUNK];
    int t0 = c * CHUNK;
    for (int i = tid; i < CHUNK * 32; i += 1024) {
        int t = i >> 5, dd = i & 31;
        int rowg = b * T + t0 + t;
        size_t base = (size_t)rowg * NPROJ;
        float m = mask[rowg];
        float qv = proj[base + 1024 + h * 32 + dd];
        float kv = proj[base + 1536 + h * 32 + dd];
        qs[t][dd] = elu1(qv) * m;
        ks[t][dd] = elu1(kv) * m;
        vs[t][dd] = proj[base + 2048 + h * 32 + dd] * m;
        if (dd == 0) ms[t] = m;
    }
    // prefix state from earlier chunks
    float S = 0.0f, kp = 0.0f;
    for (int cc = 0; cc < c; cc++) {
        const float* st = state + (size_t)(bh * NC + cc) * STATE_STRIDE;
        S += st[e * 32 + d];
        kp += st[1024 + d];
    }
    __syncthreads();
    for (int t = 0; t < CHUNK; t++) {
        float kd = ks[t][d];
        S += kd * vs[t][e];      // inclusive cumsum of k (x) v
        kp += kd;                // inclusive cumsum of k
        float qd = qs[t][d];
        float pn = qd * S;
        float pd = qd * kp;
        #pragma unroll
        for (int o = 16; o; o >>= 1) {
            pn += __shfl_xor_sync(0xffffffffu, pn, o);
            pd += __shfl_xor_sync(0xffffffffu, pd, o);
        }
        if (d == 0) {
            outa[(size_t)(b * T + t0 + t) * INNER + h * 32 + e] =
                pn / (pd + 1e-6f) * ms[t];
        }
    }
}

// ---------------------------------------------------------------------------
// Gate/residual elementwise: out1 = (inputs + sigmoid(gate)*mixed) * mask
// ---------------------------------------------------------------------------
__global__ void gate_kernel(const float* __restrict__ inp,
                            const float* __restrict__ proj,
                            const float* __restrict__ mixed,
                            const float* __restrict__ mask,
                            float* __restrict__ out1) {
    int idx = blockIdx.x * blockDim.x + threadIdx.x;
    int row = idx >> 10;
    int col = idx & (D - 1);
    float gt = proj[(size_t)row * NPROJ + col];
    float sg = 1.0f / (1.0f + expf(-gt));
    out1[idx] = (inp[idx] + sg * mixed[idx]) * mask[row];
}

// ---------------------------------------------------------------------------
// Launch
// ---------------------------------------------------------------------------
extern "C" void kernel_launch(void* const* d_in, const int* in_sizes, int n_in,
                              void* d_out, int out_size) {
    const float* inputs = (const float*)d_in[0];
    const float* mask   = (const float*)d_in[1];
    const float* ln1_g  = (const float*)d_in[2];
    const float* ln1_b  = (const float*)d_in[3];
    const float* W_in   = (const float*)d_in[4];
    const float* b_in   = (const float*)d_in[5];
    const float* W_c    = (const float*)d_in[6];
    const float* b_c    = (const float*)d_in[7];
    const float* w_t    = (const float*)d_in[8];
    const float* b_t    = (const float*)d_in[9];
    const float* w_p    = (const float*)d_in[10];
    const float* b_p    = (const float*)d_in[11];
    const float* W_mix  = (const float*)d_in[12];
    const float* b_mix  = (const float*)d_in[13];
    const float* ln2_g  = (const float*)d_in[14];
    const float* ln2_b  = (const float*)d_in[15];
    const float* W1     = (const float*)d_in[16];
    const float* b1     = (const float*)d_in[17];
    const float* W2     = (const float*)d_in[18];
    const float* b2     = (const float*)d_in[19];
    float* out = (float*)d_out;

    float *normed, *proj, *attn, *cat, *mixed, *out1, *hbuf, *ffn1, *state;
    cudaGetSymbolAddress((void**)&normed, g_normed);
    cudaGetSymbolAddress((void**)&proj,   g_proj);
    cudaGetSymbolAddress((void**)&attn,   g_attn);
    cudaGetSymbolAddress((void**)&cat,    g_cat);
    cudaGetSymbolAddress((void**)&mixed,  g_mixed);
    cudaGetSymbolAddress((void**)&out1,   g_out1);
    cudaGetSymbolAddress((void**)&hbuf,   g_h);
    cudaGetSymbolAddress((void**)&ffn1,   g_ffn1);
    cudaGetSymbolAddress((void**)&state,  g_state);

    // 1. LN1
    layernorm_kernel<<<M, 256>>>(inputs, ln1_g, ln1_b, normed);

    // 2. proj = normed @ W_in + b_in   [4096 x 2560]
    gemm_kernel<0><<<dim3(NPROJ / BN, M / BM), 256>>>(
        normed, D, W_in, NPROJ, proj, NPROJ, b_in, nullptr, 0, nullptr,
        M, NPROJ, D);

    // 3. linear attention (2-pass chunk scan)
    attn_pass1<<<B * H * NC, dim3(32, 32)>>>(proj, mask, state);
    attn_pass2<<<B * H * NC, dim3(32, 32)>>>(proj, mask, state, attn);

    // 4. content = attn @ W_c + b_c -> cat columns [0, D)
    gemm_kernel<0><<<dim3(D / BN, M / BM), 256>>>(
        attn, INNER, W_c, D, cat, 3 * D, b_c, nullptr, 0, nullptr,
        M, D, INNER);

    // 5. dwconvs -> cat columns [D, 2D) and [2D, 3D)
    dwconv_kernel<KT><<<(M * D) / 256, 256>>>(normed, w_t, b_t, cat + D);
    dwconv_kernel<KP><<<(M * D) / 256, 256>>>(normed, w_p, b_p, cat + 2 * D);

    // 6. mixed = cat @ W_mix + b_mix
    gemm_kernel<0><<<dim3(D / BN, M / BM), 256>>>(
        cat, 3 * D, W_mix, D, mixed, D, b_mix, nullptr, 0, nullptr,
        M, D, 3 * D);

    // 7. out1 = (inputs + sigmoid(gate) * mixed) * mask
    gate_kernel<<<(M * D) / 256, 256>>>(inputs, proj, mixed, mask, out1);

    // 8. LN2
    layernorm_kernel<<<M, 256>>>(out1, ln2_g, ln2_b, hbuf);

    // 9. ffn1 = gelu(h @ W1 + b1)
    gemm_kernel<1><<<dim3(FF / BN, M / BM), 256>>>(
        hbuf, D, W1, FF, ffn1, FF, b1, nullptr, 0, nullptr,
        M, FF, D);

    // 10. out = (out1 + ffn1 @ W2 + b2) * mask
    gemm_kernel<2><<<dim3(D / BN, M / BM), 256>>>(
        ffn1, FF, W2, D, out, D, b2, out1, D, mask,
        M, D, FF);
}

// round 3
// speedup vs baseline: 2.9756x; 2.9756x over previous
#include <cuda_runtime.h>
#include <cuda_bf16.h>
#include <math.h>
#include <stdint.h>

// Problem constants
constexpr int B = 2, T = 2048, D = 1024, H = 16, HD = 32, INNER = 512, FF = 4096;
constexpr int M = B * T;              // 4096 rows
constexpr int NPROJ = D + 3 * INNER;  // 2560
constexpr int KT = 3, KP = 15;
constexpr int CHUNK = 64, NC = T / CHUNK;   // 32 chunks
constexpr int STATE_STRIDE = HD * HD + HD;  // 1056 floats per (bh, chunk)

// Scratch (allocations are forbidden -> __device__ globals)
__device__ float g_normed[M * D];
__device__ float g_proj[M * NPROJ];
__device__ float g_attn[M * INNER];
__device__ float g_cat[M * 3 * D];
__device__ float g_mixed[M * D];
__device__ float g_out1[M * D];
__device__ float g_h[M * D];
__device__ float g_ffn1[(size_t)M * FF];
__device__ float g_state[B * H * NC * STATE_STRIDE];
// Transposed weights: Wt[N][K] so GEMM B operand is K-major (col-major B frag).
__device__ float g_wt_in[NPROJ * D];
__device__ float g_wt_c[D * INNER];
__device__ float g_wt_mix[D * 3 * D];
__device__ float g_wt_1[FF * D];
__device__ float g_wt_2[D * FF];

// ---------------------------------------------------------------------------
// Helpers
// ---------------------------------------------------------------------------
__device__ __forceinline__ uint32_t smem_u32(const void* p) {
    uint32_t a;
    asm("{ .reg .u64 t; cvta.to.shared.u64 t, %1; cvt.u32.u64 %0, t; }"
        : "=r"(a) : "l"(p));
    return a;
}
__device__ __forceinline__ void cp_async16(uint32_t dst, const void* src) {
    asm volatile("cp.async.cg.shared.global [%0], [%1], 16;"
                 :: "r"(dst), "l"(src));
}
__device__ __forceinline__ void cp_commit() {
    asm volatile("cp.async.commit_group;" ::: "memory");
}
template <int N>
__device__ __forceinline__ void cp_wait() {
    asm volatile("cp.async.wait_group %0;" :: "n"(N) : "memory");
}
// Round fp32 -> tf32 (rna) so the MMA's truncation is exact.
__device__ __forceinline__ float tf32r(float x) {
    uint32_t r;
    asm("cvt.rna.tf32.f32 %0, %1;" : "=r"(r) : "f"(x));
    return __uint_as_float(r);
}
__device__ __forceinline__ void mma_tf32(float* c, const uint32_t* a,
                                         const uint32_t* b) {
    asm volatile(
        "mma.sync.aligned.m16n8k8.row.col.f32.tf32.tf32.f32 "
        "{%0,%1,%2,%3}, {%4,%5,%6,%7}, {%8,%9}, {%0,%1,%2,%3};"
        : "+f"(c[0]), "+f"(c[1]), "+f"(c[2]), "+f"(c[3])
        : "r"(a[0]), "r"(a[1]), "r"(a[2]), "r"(a[3]), "r"(b[0]), "r"(b[1]));
}

// ---------------------------------------------------------------------------
// TF32 mma.sync GEMM: C[M,N] = A[M,K] @ Bt[N,K]^T (+bias, epilogue).
// CTA tile 128x128, BK=32, 8 warps (warp tile 64x32), double-buffer cp.async.
// Shared layout stride = 36 floats (conflict-free fragment loads).
// EPI 0: +bias ; EPI 1: gelu(acc+bias) ; EPI 2: (acc+bias+aux)*maskrow
// RND: round output to tf32 (for outputs feeding another GEMM's A operand).
// ---------------------------------------------------------------------------
constexpr int G_STAGE = 128 * 36;                       // floats per stage/matrix
constexpr int G_SMEM_BYTES = 4 * G_STAGE * 4;           // 73728 B

template <int EPI, bool RND>
__global__ void __launch_bounds__(256, 2)
tc_gemm(const float* __restrict__ A, int lda,
        const float* __restrict__ Bt, int ldb,   // Bt[N][K]
        float* __restrict__ C, int ldc,
        const float* __restrict__ bias,
        const float* __restrict__ aux, int ldaux,
        const float* __restrict__ mrow,
        int Kk) {
    extern __shared__ float sm[];
    float* As = sm;                  // [2][128][36]
    float* Bs = sm + 2 * G_STAGE;    // [2][128][36]
    int tid = threadIdx.x, lane = tid & 31, wid = tid >> 5;
    int wm = (wid & 1) * 64, wn = (wid >> 1) * 32;
    int m0 = blockIdx.y * 128, n0 = blockIdx.x * 128;
    int grp = lane >> 2, qid = lane & 3;

    float acc[4][4][4];
    #pragma unroll
    for (int a = 0; a < 4; a++)
        #pragma unroll
        for (int b = 0; b < 4; b++)
            #pragma unroll
            for (int c = 0; c < 4; c++) acc[a][b][c] = 0.0f;

    int row_ld = tid >> 3;           // 0..127 (wait, 256/8=32) -- see below
    // Each thread copies 4 float4 for A and 4 for B per tile:
    // idx = tid + q*256 in [0,1024): row = idx>>3, kq = (idx&7)*4.

    const int KTl = Kk >> 5;
    (void)row_ld;

    auto load_tile = [&](int kt, int s) {
        const float* Ag = A + (size_t)m0 * lda + kt * 32;
        const float* Bg = Bt + (size_t)n0 * ldb + kt * 32;
        uint32_t abase = smem_u32(As + s * G_STAGE);
        uint32_t bbase = smem_u32(Bs + s * G_STAGE);
        #pragma unroll
        for (int q = 0; q < 4; q++) {
            int idx = tid + q * 256;
            int row = idx >> 3;
            int kq = (idx & 7) * 4;
            uint32_t off = (uint32_t)(row * 36 + kq) * 4u;
            cp_async16(abase + off, Ag + (size_t)row * lda + kq);
            cp_async16(bbase + off, Bg + (size_t)row * ldb + kq);
        }
    };

    load_tile(0, 0);
    cp_commit();

    for (int i = 0; i < KTl; i++) {
        int s = i & 1;
        if (i + 1 < KTl) {
            load_tile(i + 1, s ^ 1);
            cp_commit();
            cp_wait<1>();
        } else {
            cp_wait<0>();
        }
        __syncthreads();
        const float* Asb = As + s * G_STAGE;
        const float* Bsb = Bs + s * G_STAGE;
        #pragma unroll
        for (int kk = 0; kk < 4; kk++) {
            int k = kk * 8;
            uint32_t af[4][4], bf[4][2];
            #pragma unroll
            for (int mi = 0; mi < 4; mi++) {
                const float* p = Asb + (wm + mi * 16 + grp) * 36 + k + qid;
                af[mi][0] = __float_as_uint(p[0]);
                af[mi][1] = __float_as_uint(p[8 * 36]);
                af[mi][2] = __float_as_uint(p[4]);
                af[mi][3] = __float_as_uint(p[8 * 36 + 4]);
            }
            #pragma unroll
            for (int ni = 0; ni < 4; ni++) {
                const float* p = Bsb + (wn + ni * 8 + grp) * 36 + k + qid;
                bf[ni][0] = __float_as_uint(p[0]);
                bf[ni][1] = __float_as_uint(p[4]);
            }
            #pragma unroll
            for (int mi = 0; mi < 4; mi++)
                #pragma unroll
                for (int ni = 0; ni < 4; ni++)
                    mma_tf32(acc[mi][ni], af[mi], bf[ni]);
        }
        __syncthreads();
    }

    // Epilogue
    #pragma unroll
    for (int mi = 0; mi < 4; mi++) {
        #pragma unroll
        for (int rr = 0; rr < 2; rr++) {
            int row = m0 + wm + mi * 16 + grp + rr * 8;
            float mval = 1.0f;
            if (EPI == 2) mval = mrow[row];
            #pragma unroll
            for (int ni = 0; ni < 4; ni++) {
                int col = n0 + wn + ni * 8 + 2 * qid;
                float x0 = acc[mi][ni][rr * 2 + 0] + bias[col];
                float x1 = acc[mi][ni][rr * 2 + 1] + bias[col + 1];
                if (EPI == 1) {
                    x0 = 0.5f * x0 * (1.0f + erff(x0 * 0.70710678118654752f));
                    x1 = 0.5f * x1 * (1.0f + erff(x1 * 0.70710678118654752f));
                }
                if (EPI == 2) {
                    float2 av = *(const float2*)(aux + (size_t)row * ldaux + col);
                    x0 = (x0 + av.x) * mval;
                    x1 = (x1 + av.y) * mval;
                }
                if (RND) { x0 = tf32r(x0); x1 = tf32r(x1); }
                *(float2*)(C + (size_t)row * ldc + col) = make_float2(x0, x1);
            }
        }
    }
}

// ---------------------------------------------------------------------------
// Weight transpose: dst[N][K] = src[K][N], rounded to tf32.
// ---------------------------------------------------------------------------
__global__ void transpose_kernel(const float* __restrict__ src,
                                 float* __restrict__ dst, int K, int N) {
    __shared__ float tile[32][33];
    int kb = blockIdx.y * 32, nb = blockIdx.x * 32;
    int tx = threadIdx.x, ty = threadIdx.y;
    #pragma unroll
    for (int j = 0; j < 32; j += 8)
        tile[ty + j][tx] = src[(size_t)(kb + ty + j) * N + nb + tx];
    __syncthreads();
    #pragma unroll
    for (int j = 0; j < 32; j += 8)
        dst[(size_t)(nb + ty + j) * K + kb + tx] = tf32r(tile[tx][ty + j]);
}

// ---------------------------------------------------------------------------
// LayerNorm: one block per row (D=1024), 256 threads, float4 per thread.
// Output rounded to tf32 (feeds GEMM A operands).
// ---------------------------------------------------------------------------
__global__ void layernorm_kernel(const float* __restrict__ x,
                                 const float* __restrict__ g,
                                 const float* __restrict__ bta,
                                 float* __restrict__ y) {
    int row = blockIdx.x;
    int tid = threadIdx.x;
    float4 v = ((const float4*)(x + (size_t)row * D))[tid];
    float s = v.x + v.y + v.z + v.w;
    float sq = v.x * v.x + v.y * v.y + v.z * v.z + v.w * v.w;
    __shared__ float ss[256], sv[256];
    ss[tid] = s; sv[tid] = sq;
    __syncthreads();
    #pragma unroll
    for (int o = 128; o; o >>= 1) {
        if (tid < o) { ss[tid] += ss[tid + o]; sv[tid] += sv[tid + o]; }
        __syncthreads();
    }
    float mu = ss[0] * (1.0f / D);
    float var = sv[0] * (1.0f / D) - mu * mu;
    float rstd = rsqrtf(var + 1e-5f);
    int c = tid * 4;
    float4 gv = *(const float4*)(g + c);
    float4 bv = *(const float4*)(bta + c);
    float4 o;
    o.x = tf32r((v.x - mu) * rstd * gv.x + bv.x);
    o.y = tf32r((v.y - mu) * rstd * gv.y + bv.y);
    o.z = tf32r((v.z - mu) * rstd * gv.z + bv.z);
    o.w = tf32r((v.w - mu) * rstd * gv.w + bv.w);
    ((float4*)(y + (size_t)row * D))[tid] = o;
}

// ---------------------------------------------------------------------------
// Causal depthwise conv over time. Output rounded to tf32 (feeds mixed GEMM).
// ---------------------------------------------------------------------------
template <int KW>
__global__ void dwconv_kernel(const float* __restrict__ x,
                              const float* __restrict__ w,
                              const float* __restrict__ bias,
                              float* __restrict__ y /* pre-offset, stride 3D */) {
    int idx = blockIdx.x * blockDim.x + threadIdx.x;  // over M*D
    int d = idx & (D - 1);
    int bt = idx >> 10;
    int t = bt & (T - 1);
    float acc = bias[d];
    #pragma unroll
    for (int j = 0; j < KW; j++) {
        int tt = t - (KW - 1) + j;
        if (tt >= 0)
            acc += w[d * KW + j] * x[((size_t)(bt - (KW - 1) + j)) * D + d];
    }
    y[(size_t)bt * (3 * D) + d] = tf32r(acc);
}

// ---------------------------------------------------------------------------
// Linear attention, chunked scan (unchanged except tf32-rounded output).
// ---------------------------------------------------------------------------
__device__ __forceinline__ float elu1(float x) {
    return x > 0.0f ? x + 1.0f : expf(x);
}

__global__ void __launch_bounds__(1024)
attn_pass1(const float* __restrict__ proj, const float* __restrict__ mask,
           float* __restrict__ state) {
    int bh = blockIdx.x / NC, c = blockIdx.x % NC;
    int b = bh / H, h = bh % H;
    int d = threadIdx.x, e = threadIdx.y;
    int tid = e * 32 + d;
    __shared__ float ks[CHUNK][32];
    __shared__ float vs[CHUNK][32];
    int t0 = c * CHUNK;
    for (int i = tid; i < CHUNK * 32; i += 1024) {
        int t = i >> 5, dd = i & 31;
        int rowg = b * T + t0 + t;
        size_t base = (size_t)rowg * NPROJ;
        float m = mask[rowg];
        float kv = proj[base + 1536 + h * 32 + dd];
        ks[t][dd] = elu1(kv) * m;
        vs[t][dd] = proj[base + 2048 + h * 32 + dd] * m;
    }
    __syncthreads();
    float S = 0.0f, kp = 0.0f;
    #pragma unroll 4
    for (int t = 0; t < CHUNK; t++) {
        float kd = ks[t][d];
        S += kd * vs[t][e];
        kp += kd;
    }
    float* st = state + (size_t)blockIdx.x * STATE_STRIDE;
    st[e * 32 + d] = S;
    if (e == 0) st[1024 + d] = kp;
}

__global__ void __launch_bounds__(1024)
attn_pass2(const float* __restrict__ proj, const float* __restrict__ mask,
           const float* __restrict__ state, float* __restrict__ outa) {
    int bh = blockIdx.x / NC, c = blockIdx.x % NC;
    int b = bh / H, h = bh % H;
    int d = threadIdx.x, e = threadIdx.y;
    int tid = e * 32 + d;
    __shared__ float qs[CHUNK][32];
    __shared__ float ks[CHUNK][32];
    __shared__ float vs[CHUNK][32];
    __shared__ float ms[CHUNK];
    int t0 = c * CHUNK;
    for (int i = tid; i < CHUNK * 32; i += 1024) {
        int t = i >> 5, dd = i & 31;
        int rowg = b * T + t0 + t;
        size_t base = (size_t)rowg * NPROJ;
        float m = mask[rowg];
        float qv = proj[base + 1024 + h * 32 + dd];
        float kv = proj[base + 1536 + h * 32 + dd];
        qs[t][dd] = elu1(qv) * m;
        ks[t][dd] = elu1(kv) * m;
        vs[t][dd] = proj[base + 2048 + h * 32 + dd] * m;
        if (dd == 0) ms[t] = m;
    }
    float S = 0.0f, kp = 0.0f;
    for (int cc = 0; cc < c; cc++) {
        const float* st = state + (size_t)(bh * NC + cc) * STATE_STRIDE;
        S += st[e * 32 + d];
        kp += st[1024 + d];
    }
    __syncthreads();
    for (int t = 0; t < CHUNK; t++) {
        float kd = ks[t][d];
        S += kd * vs[t][e];
        kp += kd;
        float qd = qs[t][d];
        float pn = qd * S;
        float pd = qd * kp;
        #pragma unroll
        for (int o = 16; o; o >>= 1) {
            pn += __shfl_xor_sync(0xffffffffu, pn, o);
            pd += __shfl_xor_sync(0xffffffffu, pd, o);
        }
        if (d == 0) {
            outa[(size_t)(b * T + t0 + t) * INNER + h * 32 + e] =
                tf32r(pn / (pd + 1e-6f) * ms[t]);
        }
    }
}

// ---------------------------------------------------------------------------
// Gate/residual elementwise: out1 = (inputs + sigmoid(gate)*mixed) * mask
// ---------------------------------------------------------------------------
__global__ void gate_kernel(const float* __restrict__ inp,
                            const float* __restrict__ proj,
                            const float* __restrict__ mixed,
                            const float* __restrict__ mask,
                            float* __restrict__ out1) {
    int idx = blockIdx.x * blockDim.x + threadIdx.x;
    int row = idx >> 10;
    int col = idx & (D - 1);
    float gt = proj[(size_t)row * NPROJ + col];
    float sg = 1.0f / (1.0f + expf(-gt));
    out1[idx] = (inp[idx] + sg * mixed[idx]) * mask[row];
}

// ---------------------------------------------------------------------------
// Launch
// ---------------------------------------------------------------------------
extern "C" void kernel_launch(void* const* d_in, const int* in_sizes, int n_in,
                              void* d_out, int out_size) {
    const float* inputs = (const float*)d_in[0];
    const float* mask   = (const float*)d_in[1];
    const float* ln1_g  = (const float*)d_in[2];
    const float* ln1_b  = (const float*)d_in[3];
    const float* W_in   = (const float*)d_in[4];
    const float* b_in   = (const float*)d_in[5];
    const float* W_c    = (const float*)d_in[6];
    const float* b_c    = (const float*)d_in[7];
    const float* w_t    = (const float*)d_in[8];
    const float* b_t    = (const float*)d_in[9];
    const float* w_p    = (const float*)d_in[10];
    const float* b_p    = (const float*)d_in[11];
    const float* W_mix  = (const float*)d_in[12];
    const float* b_mix  = (const float*)d_in[13];
    const float* ln2_g  = (const float*)d_in[14];
    const float* ln2_b  = (const float*)d_in[15];
    const float* W1     = (const float*)d_in[16];
    const float* b1     = (const float*)d_in[17];
    const float* W2     = (const float*)d_in[18];
    const float* b2     = (const float*)d_in[19];
    float* out = (float*)d_out;

    float *normed, *proj, *attn, *cat, *mixed, *out1, *hbuf, *ffn1, *state;
    float *wt_in, *wt_c, *wt_mix, *wt_1, *wt_2;
    cudaGetSymbolAddress((void**)&normed, g_normed);
    cudaGetSymbolAddress((void**)&proj,   g_proj);
    cudaGetSymbolAddress((void**)&attn,   g_attn);
    cudaGetSymbolAddress((void**)&cat,    g_cat);
    cudaGetSymbolAddress((void**)&mixed,  g_mixed);
    cudaGetSymbolAddress((void**)&out1,   g_out1);
    cudaGetSymbolAddress((void**)&hbuf,   g_h);
    cudaGetSymbolAddress((void**)&ffn1,   g_ffn1);
    cudaGetSymbolAddress((void**)&state,  g_state);
    cudaGetSymbolAddress((void**)&wt_in,  g_wt_in);
    cudaGetSymbolAddress((void**)&wt_c,   g_wt_c);
    cudaGetSymbolAddress((void**)&wt_mix, g_wt_mix);
    cudaGetSymbolAddress((void**)&wt_1,   g_wt_1);
    cudaGetSymbolAddress((void**)&wt_2,   g_wt_2);

    cudaFuncSetAttribute(tc_gemm<0, false>, cudaFuncAttributeMaxDynamicSharedMemorySize, G_SMEM_BYTES);
    cudaFuncSetAttribute(tc_gemm<0, true>,  cudaFuncAttributeMaxDynamicSharedMemorySize, G_SMEM_BYTES);
    cudaFuncSetAttribute(tc_gemm<1, true>,  cudaFuncAttributeMaxDynamicSharedMemorySize, G_SMEM_BYTES);
    cudaFuncSetAttribute(tc_gemm<2, false>, cudaFuncAttributeMaxDynamicSharedMemorySize, G_SMEM_BYTES);

    dim3 tb(32, 8);
    transpose_kernel<<<dim3(NPROJ / 32, D / 32), tb>>>(W_in, wt_in, D, NPROJ);
    transpose_kernel<<<dim3(D / 32, INNER / 32), tb>>>(W_c, wt_c, INNER, D);
    transpose_kernel<<<dim3(D / 32, (3 * D) / 32), tb>>>(W_mix, wt_mix, 3 * D, D);
    transpose_kernel<<<dim3(FF / 32, D / 32), tb>>>(W1, wt_1, D, FF);
    transpose_kernel<<<dim3(D / 32, FF / 32), tb>>>(W2, wt_2, FF, D);

    // 1. LN1
    layernorm_kernel<<<M, 256>>>(inputs, ln1_g, ln1_b, normed);

    // 2. proj = normed @ W_in + b_in
    tc_gemm<0, false><<<dim3(NPROJ / 128, M / 128), 256, G_SMEM_BYTES>>>(
        normed, D, wt_in, D, proj, NPROJ, b_in, nullptr, 0, nullptr, D);

    // 3. linear attention
    attn_pass1<<<B * H * NC, dim3(32, 32)>>>(proj, mask, state);
    attn_pass2<<<B * H * NC, dim3(32, 32)>>>(proj, mask, state, attn);

    // 4. content = attn @ W_c + b_c -> cat[:, 0:D]
    tc_gemm<0, true><<<dim3(D / 128, M / 128), 256, G_SMEM_BYTES>>>(
        attn, INNER, wt_c, INNER, cat, 3 * D, b_c, nullptr, 0, nullptr, INNER);

    // 5. dwconvs -> cat[:, D:2D] and cat[:, 2D:3D]
    dwconv_kernel<KT><<<(M * D) / 256, 256>>>(normed, w_t, b_t, cat + D);
    dwconv_kernel<KP><<<(M * D) / 256, 256>>>(normed, w_p, b_p, cat + 2 * D);

    // 6. mixed = cat @ W_mix + b_mix
    tc_gemm<0, false><<<dim3(D / 128, M / 128), 256, G_SMEM_BYTES>>>(
        cat, 3 * D, wt_mix, 3 * D, mixed, D, b_mix, nullptr, 0, nullptr, 3 * D);

    // 7. out1 = (inputs + sigmoid(gate) * mixed) * mask
    gate_kernel<<<(M * D) / 256, 256>>>(inputs, proj, mixed, mask, out1);

    // 8. LN2
    layernorm_kernel<<<M, 256>>>(out1, ln2_g, ln2_b, hbuf);

    // 9. ffn1 = gelu(h @ W1 + b1)
    tc_gemm<1, true><<<dim3(FF / 128, M / 128), 256, G_SMEM_BYTES>>>(
        hbuf, D, wt_1, D, ffn1, FF, b1, nullptr, 0, nullptr, D);

    // 10. out = (out1 + ffn1 @ W2 + b2) * mask
    tc_gemm<2, false><<<dim3(D / 128, M / 128), 256, G_SMEM_BYTES>>>(
        ffn1, FF, wt_2, FF, out, D, b2, out1, D, mask, FF);
}

// round 4
// speedup vs baseline: 3.3058x; 1.1110x over previous
#include <cuda_runtime.h>
#include <cuda_bf16.h>
#include <math.h>
#include <stdint.h>

// Problem constants
constexpr int B = 2, T = 2048, D = 1024, H = 16, HD = 32, INNER = 512, FF = 4096;
constexpr int M = B * T;              // 4096 rows
constexpr int NPROJ = D + 3 * INNER;  // 2560
constexpr int KT = 3, KP = 15;
constexpr int CHUNK = 64, NC = T / CHUNK;   // 32 chunks
constexpr int STATE_STRIDE = HD * HD + HD;  // 1056 floats per (bh, chunk)

// Scratch (allocations are forbidden -> __device__ globals)
__device__ float g_normed[M * D];
__device__ float g_proj[M * NPROJ];
__device__ float g_attn[M * INNER];
__device__ float g_cat[M * 3 * D];
__device__ float g_mixed[M * D];
__device__ float g_out1[M * D];
__device__ float g_h[M * D];
__device__ float g_ffn1[(size_t)M * FF];
__device__ float g_state[B * H * NC * STATE_STRIDE];
__device__ float g_state2[B * H * NC * STATE_STRIDE];  // exclusive prefixes

// ---------------------------------------------------------------------------
// Helpers
// ---------------------------------------------------------------------------
__device__ __forceinline__ uint32_t smem_u32(const void* p) {
    uint32_t a;
    asm("{ .reg .u64 t; cvta.to.shared.u64 t, %1; cvt.u32.u64 %0, t; }"
        : "=r"(a) : "l"(p));
    return a;
}
__device__ __forceinline__ void cp_async16(uint32_t dst, const void* src) {
    asm volatile("cp.async.cg.shared.global [%0], [%1], 16;"
                 :: "r"(dst), "l"(src));
}
__device__ __forceinline__ void cp_commit() {
    asm volatile("cp.async.commit_group;" ::: "memory");
}
template <int N>
__device__ __forceinline__ void cp_wait() {
    asm volatile("cp.async.wait_group %0;" :: "n"(N) : "memory");
}
// Round fp32 -> tf32 (rna) so the MMA's truncation is exact.
__device__ __forceinline__ float tf32r(float x) {
    uint32_t r;
    asm("cvt.rna.tf32.f32 %0, %1;" : "=r"(r) : "f"(x));
    return __uint_as_float(r);
}
__device__ __forceinline__ void mma_tf32(float* c, const uint32_t* a,
                                         const uint32_t* b) {
    asm volatile(
        "mma.sync.aligned.m16n8k8.row.col.f32.tf32.tf32.f32 "
        "{%0,%1,%2,%3}, {%4,%5,%6,%7}, {%8,%9}, {%0,%1,%2,%3};"
        : "+f"(c[0]), "+f"(c[1]), "+f"(c[2]), "+f"(c[3])
        : "r"(a[0]), "r"(a[1]), "r"(a[2]), "r"(a[3]), "r"(b[0]), "r"(b[1]));
}

// ---------------------------------------------------------------------------
// TF32 mma.sync GEMM: C[M,N] = A[M,K] @ W[K,N] (+bias, epilogue).
// CTA tile 128x128, BK=32, 8 warps (warp tile 64x32), double-buffer cp.async.
// A smem: [128][36] (conflict-free A frags), B smem: [32][136] (conflict-free
// B frags loaded straight from W's [K][N] layout -- no host-side transpose).
// EPI 0: +bias ; EPI 1: gelu(acc+bias) ; EPI 2: (acc+bias+aux)*maskrow
// RND: round output to tf32 (for outputs feeding another GEMM's A operand).
// ---------------------------------------------------------------------------
constexpr int A_STAGE = 128 * 36;   // floats
constexpr int B_STAGE = 32 * 136;   // floats
constexpr int G_SMEM_BYTES = (2 * A_STAGE + 2 * B_STAGE) * 4;  // 71680 B

template <int EPI, bool RND>
__global__ void __launch_bounds__(256, 2)
tc_gemm(const float* __restrict__ A, int lda,
        const float* __restrict__ Bw, int ldb,   // W[K][N], ldb = row stride
        float* __restrict__ C, int ldc,
        const float* __restrict__ bias,
        const float* __restrict__ aux, int ldaux,
        const float* __restrict__ mrow,
        int Kk) {
    extern __shared__ float sm[];
    float* Asm = sm;                    // [2][128][36]
    float* Bsm = sm + 2 * A_STAGE;      // [2][32][136]
    int tid = threadIdx.x, lane = tid & 31, wid = tid >> 5;
    int wm = (wid & 1) * 64, wn = (wid >> 1) * 32;
    int m0 = blockIdx.y * 128, n0 = blockIdx.x * 128;
    int grp = lane >> 2, qid = lane & 3;

    float acc[4][4][4];
    #pragma unroll
    for (int a = 0; a < 4; a++)
        #pragma unroll
        for (int b = 0; b < 4; b++)
            #pragma unroll
            for (int c = 0; c < 4; c++) acc[a][b][c] = 0.0f;

    const int KTl = Kk >> 5;

    auto load_tile = [&](int kt, int s) {
        const float* Ag = A + (size_t)m0 * lda + kt * 32;
        const float* Bg = Bw + (size_t)(kt * 32) * ldb + n0;
        uint32_t abase = smem_u32(Asm + s * A_STAGE);
        uint32_t bbase = smem_u32(Bsm + s * B_STAGE);
        #pragma unroll
        for (int q = 0; q < 4; q++) {
            int idx = tid + q * 256;
            int arow = idx >> 3, akq = (idx & 7) * 4;
            cp_async16(abase + (uint32_t)(arow * 36 + akq) * 4u,
                       Ag + (size_t)arow * lda + akq);
            int brow = idx >> 5, bc = (idx & 31) * 4;
            cp_async16(bbase + (uint32_t)(brow * 136 + bc) * 4u,
                       Bg + (size_t)brow * ldb + bc);
        }
    };

    load_tile(0, 0);
    cp_commit();

    for (int i = 0; i < KTl; i++) {
        int s = i & 1;
        if (i + 1 < KTl) {
            load_tile(i + 1, s ^ 1);
            cp_commit();
            cp_wait<1>();
        } else {
            cp_wait<0>();
        }
        __syncthreads();
        const float* Asb = Asm + s * A_STAGE;
        const float* Bsb = Bsm + s * B_STAGE;
        #pragma unroll
        for (int kk = 0; kk < 4; kk++) {
            int k = kk * 8;
            uint32_t af[4][4], bf[4][2];
            #pragma unroll
            for (int mi = 0; mi < 4; mi++) {
                const float* p = Asb + (wm + mi * 16 + grp) * 36 + k + qid;
                af[mi][0] = __float_as_uint(p[0]);
                af[mi][1] = __float_as_uint(p[8 * 36]);
                af[mi][2] = __float_as_uint(p[4]);
                af[mi][3] = __float_as_uint(p[8 * 36 + 4]);
            }
            #pragma unroll
            for (int ni = 0; ni < 4; ni++) {
                int col = wn + ni * 8 + grp;
                bf[ni][0] = __float_as_uint(tf32r(Bsb[(k + qid) * 136 + col]));
                bf[ni][1] = __float_as_uint(tf32r(Bsb[(k + qid + 4) * 136 + col]));
            }
            #pragma unroll
            for (int mi = 0; mi < 4; mi++)
                #pragma unroll
                for (int ni = 0; ni < 4; ni++)
                    mma_tf32(acc[mi][ni], af[mi], bf[ni]);
        }
        __syncthreads();
    }

    // Epilogue
    #pragma unroll
    for (int mi = 0; mi < 4; mi++) {
        #pragma unroll
        for (int rr = 0; rr < 2; rr++) {
            int row = m0 + wm + mi * 16 + grp + rr * 8;
            float mval = 1.0f;
            if (EPI == 2) mval = mrow[row];
            #pragma unroll
            for (int ni = 0; ni < 4; ni++) {
                int col = n0 + wn + ni * 8 + 2 * qid;
                float x0 = acc[mi][ni][rr * 2 + 0] + bias[col];
                float x1 = acc[mi][ni][rr * 2 + 1] + bias[col + 1];
                if (EPI == 1) {
                    x0 = 0.5f * x0 * (1.0f + erff(x0 * 0.70710678118654752f));
                    x1 = 0.5f * x1 * (1.0f + erff(x1 * 0.70710678118654752f));
                }
                if (EPI == 2) {
                    float2 av = *(const float2*)(aux + (size_t)row * ldaux + col);
                    x0 = (x0 + av.x) * mval;
                    x1 = (x1 + av.y) * mval;
                }
                if (RND) { x0 = tf32r(x0); x1 = tf32r(x1); }
                *(float2*)(C + (size_t)row * ldc + col) = make_float2(x0, x1);
            }
        }
    }
}

// ---------------------------------------------------------------------------
// LayerNorm (output tf32-rounded: feeds GEMM A operands).
// ---------------------------------------------------------------------------
__global__ void layernorm_kernel(const float* __restrict__ x,
                                 const float* __restrict__ g,
                                 const float* __restrict__ bta,
                                 float* __restrict__ y) {
    int row = blockIdx.x;
    int tid = threadIdx.x;
    float4 v = ((const float4*)(x + (size_t)row * D))[tid];
    float s = v.x + v.y + v.z + v.w;
    float sq = v.x * v.x + v.y * v.y + v.z * v.z + v.w * v.w;
    __shared__ float ss[256], sv[256];
    ss[tid] = s; sv[tid] = sq;
    __syncthreads();
    #pragma unroll
    for (int o = 128; o; o >>= 1) {
        if (tid < o) { ss[tid] += ss[tid + o]; sv[tid] += sv[tid + o]; }
        __syncthreads();
    }
    float mu = ss[0] * (1.0f / D);
    float var = sv[0] * (1.0f / D) - mu * mu;
    float rstd = rsqrtf(var + 1e-5f);
    int c = tid * 4;
    float4 gv = *(const float4*)(g + c);
    float4 bv = *(const float4*)(bta + c);
    float4 o;
    o.x = tf32r((v.x - mu) * rstd * gv.x + bv.x);
    o.y = tf32r((v.y - mu) * rstd * gv.y + bv.y);
    o.z = tf32r((v.z - mu) * rstd * gv.z + bv.z);
    o.w = tf32r((v.w - mu) * rstd * gv.w + bv.w);
    ((float4*)(y + (size_t)row * D))[tid] = o;
}

// ---------------------------------------------------------------------------
// Causal depthwise conv over time (tf32-rounded output, feeds mixed GEMM).
// ---------------------------------------------------------------------------
template <int KW>
__global__ void dwconv_kernel(const float* __restrict__ x,
                              const float* __restrict__ w,
                              const float* __restrict__ bias,
                              float* __restrict__ y /* pre-offset, stride 3D */) {
    int idx = blockIdx.x * blockDim.x + threadIdx.x;  // over M*D
    int d = idx & (D - 1);
    int bt = idx >> 10;
    int t = bt & (T - 1);
    float acc = bias[d];
    #pragma unroll
    for (int j = 0; j < KW; j++) {
        int tt = t - (KW - 1) + j;
        if (tt >= 0)
            acc += w[d * KW + j] * x[((size_t)(bt - (KW - 1) + j)) * D + d];
    }
    y[(size_t)bt * (3 * D) + d] = tf32r(acc);
}

// ---------------------------------------------------------------------------
// Linear attention, chunked. Pass 1: per-chunk local sums (unchanged).
// Scan: exclusive prefix of chunk states. Pass 2: fully parallel intra-chunk
// matmul formulation (no sequential scan, no shuffle reductions).
// ---------------------------------------------------------------------------
__device__ __forceinline__ float elu1(float x) {
    return x > 0.0f ? x + 1.0f : expf(x);
}

__global__ void __launch_bounds__(1024)
attn_pass1(const float* __restrict__ proj, const float* __restrict__ mask,
           float* __restrict__ state) {
    int bh = blockIdx.x / NC, c = blockIdx.x % NC;
    int b = bh / H, h = bh % H;
    int d = threadIdx.x, e = threadIdx.y;
    int tid = e * 32 + d;
    __shared__ float ks[CHUNK][32];
    __shared__ float vs[CHUNK][32];
    int t0 = c * CHUNK;
    for (int i = tid; i < CHUNK * 32; i += 1024) {
        int t = i >> 5, dd = i & 31;
        int rowg = b * T + t0 + t;
        size_t base = (size_t)rowg * NPROJ;
        float m = mask[rowg];
        float kv = proj[base + 1536 + h * 32 + dd];
        ks[t][dd] = elu1(kv) * m;
        vs[t][dd] = proj[base + 2048 + h * 32 + dd] * m;
    }
    __syncthreads();
    float S = 0.0f, kp = 0.0f;
    #pragma unroll 4
    for (int t = 0; t < CHUNK; t++) {
        float kd = ks[t][d];
        S += kd * vs[t][e];
        kp += kd;
    }
    float* st = state + (size_t)blockIdx.x * STATE_STRIDE;
    st[e * 32 + d] = S;
    if (e == 0) st[1024 + d] = kp;
}

// Exclusive prefix over chunks: st2[bh][c] = sum_{cc<c} st[bh][cc]
__global__ void scan_state(const float* __restrict__ st,
                           float* __restrict__ st2) {
    int bh = blockIdx.x;  // B*H = 32
    for (int i = threadIdx.x; i < STATE_STRIDE; i += blockDim.x) {
        float acc = 0.0f;
        for (int c = 0; c < NC; c++) {
            size_t idx = ((size_t)(bh * NC + c)) * STATE_STRIDE + i;
            st2[idx] = acc;
            acc += st[idx];
        }
    }
}

__global__ void __launch_bounds__(256)
attn_pass2(const float* __restrict__ proj, const float* __restrict__ mask,
           const float* __restrict__ st2, float* __restrict__ outa) {
    int bh = blockIdx.x / NC, c = blockIdx.x % NC;
    int b = bh / H, h = bh % H;
    int tid = threadIdx.x;
    __shared__ float qs[CHUNK][36];
    __shared__ float ks[CHUNK][36];
    __shared__ float vs[CHUNK][33];
    __shared__ float Aa[CHUNK][CHUNK];
    __shared__ float Ps[32][33];
    __shared__ float kpp[32];
    __shared__ float ms[CHUNK];
    int t0 = c * CHUNK;

    // Phase 0: stage q,k,v (elu+mask applied), prefix state, mask
    for (int i = tid; i < CHUNK * 32; i += 256) {
        int t = i >> 5, dd = i & 31;
        int rowg = b * T + t0 + t;
        size_t base = (size_t)rowg * NPROJ;
        float m = mask[rowg];
        qs[t][dd] = elu1(proj[base + 1024 + h * 32 + dd]) * m;
        ks[t][dd] = elu1(proj[base + 1536 + h * 32 + dd]) * m;
        vs[t][dd] = proj[base + 2048 + h * 32 + dd] * m;
        if (dd == 0) ms[t] = m;
    }
    const float* stp = st2 + (size_t)blockIdx.x * STATE_STRIDE;
    for (int i = tid; i < 1024; i += 256) {
        int d = i & 31, e = i >> 5;
        Ps[d][e] = stp[i];   // stored as st[e*32+d]
    }
    if (tid < 32) kpp[tid] = stp[1024 + tid];
    __syncthreads();

    // Phase 1: A[t][tp] = q[t] . k[tp]  (64x64, K=32), 4x4 per thread
    {
        int ty = tid >> 4, tx = tid & 15;
        int r0 = ty * 4, c0 = tx * 4;
        float a4[4][4] = {};
        #pragma unroll
        for (int d0 = 0; d0 < 32; d0 += 4) {
            float4 qr[4], kr[4];
            #pragma unroll
            for (int i = 0; i < 4; i++)
                qr[i] = *(const float4*)&qs[r0 + i][d0];
            #pragma unroll
            for (int j = 0; j < 4; j++)
                kr[j] = *(const float4*)&ks[c0 + j][d0];
            #pragma unroll
            for (int i = 0; i < 4; i++)
                #pragma unroll
                for (int j = 0; j < 4; j++)
                    a4[i][j] += qr[i].x * kr[j].x + qr[i].y * kr[j].y
                              + qr[i].z * kr[j].z + qr[i].w * kr[j].w;
        }
        #pragma unroll
        for (int i = 0; i < 4; i++)
            #pragma unroll
            for (int j = 0; j < 4; j++)
                Aa[r0 + i][c0 + j] = a4[i][j];
    }
    __syncthreads();

    // Phase 2: out[t][e] = (q[t].P[:,e] + sum_{tp<=t} A[t][tp] v[tp][e])
    //                     / (q[t].kpp + sum_{tp<=t} A[t][tp] + 1e-6) * m[t]
    int w = tid >> 5, e = tid & 31;
    #pragma unroll
    for (int ii = 0; ii < 8; ii++) {
        int t = w + 8 * ii;
        float num = 0.0f, den = 0.0f;
        #pragma unroll
        for (int d = 0; d < 32; d++) {
            float qd = qs[t][d];
            num += qd * Ps[d][e];
            den += qd * kpp[d];
        }
        const float* Arow = Aa[t];
        for (int tp = 0; tp <= t; tp++) {
            float a = Arow[tp];
            num += a * vs[tp][e];
            den += a;
        }
        outa[(size_t)(b * T + t0 + t) * INNER + h * 32 + e] =
            tf32r(num / (den + 1e-6f) * ms[t]);
    }
}

// ---------------------------------------------------------------------------
// Gate/residual elementwise: out1 = (inputs + sigmoid(gate)*mixed) * mask
// ---------------------------------------------------------------------------
__global__ void gate_kernel(const float* __restrict__ inp,
                            const float* __restrict__ proj,
                            const float* __restrict__ mixed,
                            const float* __restrict__ mask,
                            float* __restrict__ out1) {
    int idx = blockIdx.x * blockDim.x + threadIdx.x;
    int row = idx >> 10;
    int col = idx & (D - 1);
    float gt = proj[(size_t)row * NPROJ + col];
    float sg = 1.0f / (1.0f + expf(-gt));
    out1[idx] = (inp[idx] + sg * mixed[idx]) * mask[row];
}

// ---------------------------------------------------------------------------
// Launch
// ---------------------------------------------------------------------------
extern "C" void kernel_launch(void* const* d_in, const int* in_sizes, int n_in,
                              void* d_out, int out_size) {
    const float* inputs = (const float*)d_in[0];
    const float* mask   = (const float*)d_in[1];
    const float* ln1_g  = (const float*)d_in[2];
    const float* ln1_b  = (const float*)d_in[3];
    const float* W_in   = (const float*)d_in[4];
    const float* b_in   = (const float*)d_in[5];
    const float* W_c    = (const float*)d_in[6];
    const float* b_c    = (const float*)d_in[7];
    const float* w_t    = (const float*)d_in[8];
    const float* b_t    = (const float*)d_in[9];
    const float* w_p    = (const float*)d_in[10];
    const float* b_p    = (const float*)d_in[11];
    const float* W_mix  = (const float*)d_in[12];
    const float* b_mix  = (const float*)d_in[13];
    const float* ln2_g  = (const float*)d_in[14];
    const float* ln2_b  = (const float*)d_in[15];
    const float* W1     = (const float*)d_in[16];
    const float* b1     = (const float*)d_in[17];
    const float* W2     = (const float*)d_in[18];
    const float* b2     = (const float*)d_in[19];
    float* out = (float*)d_out;

    float *normed, *proj, *attn, *cat, *mixed, *out1, *hbuf, *ffn1;
    float *state, *state2;
    cudaGetSymbolAddress((void**)&normed, g_normed);
    cudaGetSymbolAddress((void**)&proj,   g_proj);
    cudaGetSymbolAddress((void**)&attn,   g_attn);
    cudaGetSymbolAddress((void**)&cat,    g_cat);
    cudaGetSymbolAddress((void**)&mixed,  g_mixed);
    cudaGetSymbolAddress((void**)&out1,   g_out1);
    cudaGetSymbolAddress((void**)&hbuf,   g_h);
    cudaGetSymbolAddress((void**)&ffn1,   g_ffn1);
    cudaGetSymbolAddress((void**)&state,  g_state);
    cudaGetSymbolAddress((void**)&state2, g_state2);

    cudaFuncSetAttribute(tc_gemm<0, false>, cudaFuncAttributeMaxDynamicSharedMemorySize, G_SMEM_BYTES);
    cudaFuncSetAttribute(tc_gemm<0, true>,  cudaFuncAttributeMaxDynamicSharedMemorySize, G_SMEM_BYTES);
    cudaFuncSetAttribute(tc_gemm<1, true>,  cudaFuncAttributeMaxDynamicSharedMemorySize, G_SMEM_BYTES);
    cudaFuncSetAttribute(tc_gemm<2, false>, cudaFuncAttributeMaxDynamicSharedMemorySize, G_SMEM_BYTES);

    // 1. LN1
    layernorm_kernel<<<M, 256>>>(inputs, ln1_g, ln1_b, normed);

    // 2. proj = normed @ W_in + b_in
    tc_gemm<0, false><<<dim3(NPROJ / 128, M / 128), 256, G_SMEM_BYTES>>>(
        normed, D, W_in, NPROJ, proj, NPROJ, b_in, nullptr, 0, nullptr, D);

    // 3. linear attention (pass1 -> prefix scan -> parallel pass2)
    attn_pass1<<<B * H * NC, dim3(32, 32)>>>(proj, mask, state);
    scan_state<<<B * H, 1024>>>(state, state2);
    attn_pass2<<<B * H * NC, 256>>>(proj, mask, state2, attn);

    // 4. content = attn @ W_c + b_c -> cat[:, 0:D]
    tc_gemm<0, true><<<dim3(D / 128, M / 128), 256, G_SMEM_BYTES>>>(
        attn, INNER, W_c, D, cat, 3 * D, b_c, nullptr, 0, nullptr, INNER);

    // 5. dwconvs -> cat[:, D:2D] and cat[:, 2D:3D]
    dwconv_kernel<KT><<<(M * D) / 256, 256>>>(normed, w_t, b_t, cat + D);
    dwconv_kernel<KP><<<(M * D) / 256, 256>>>(normed, w_p, b_p, cat + 2 * D);

    // 6. mixed = cat @ W_mix + b_mix
    tc_gemm<0, false><<<dim3(D / 128, M / 128), 256, G_SMEM_BYTES>>>(
        cat, 3 * D, W_mix, D, mixed, D, b_mix, nullptr, 0, nullptr, 3 * D);

    // 7. out1 = (inputs + sigmoid(gate) * mixed) * mask
    gate_kernel<<<(M * D) / 256, 256>>>(inputs, proj, mixed, mask, out1);

    // 8. LN2
    layernorm_kernel<<<M, 256>>>(out1, ln2_g, ln2_b, hbuf);

    // 9. ffn1 = gelu(h @ W1 + b1)
    tc_gemm<1, true><<<dim3(FF / 128, M / 128), 256, G_SMEM_BYTES>>>(
        hbuf, D, W1, FF, ffn1, FF, b1, nullptr, 0, nullptr, D);

    // 10. out = (out1 + ffn1 @ W2 + b2) * mask
    tc_gemm<2, false><<<dim3(D / 128, M / 128), 256, G_SMEM_BYTES>>>(
        ffn1, FF, W2, D, out, D, b2, out1, D, mask, FF);
}

// round 5
// speedup vs baseline: 4.6765x; 1.4146x over previous
#include <cuda_runtime.h>
#include <cuda_fp16.h>
#include <math.h>
#include <stdint.h>

// Problem constants
constexpr int B = 2, T = 2048, D = 1024, H = 16, HD = 32, INNER = 512, FF = 4096;
constexpr int M = B * T;              // 4096 rows
constexpr int NPROJ = D + 3 * INNER;  // 2560
constexpr int KT = 3, KP = 15;
constexpr int CHUNK = 64, NC = T / CHUNK;   // 32 chunks
constexpr int STATE_STRIDE = HD * HD + HD;  // 1056 floats per (bh, chunk)

// Scratch (allocations are forbidden -> __device__ globals)
__device__ float g_proj[M * NPROJ];
__device__ float g_mixed[M * D];
__device__ float g_out1[M * D];
__device__ float g_state[B * H * NC * STATE_STRIDE];
__device__ float g_state2[B * H * NC * STATE_STRIDE];
// Half activations (GEMM A operands)
__device__ __half h_normed[M * D];
__device__ __half h_attn[M * INNER];
__device__ __half h_cat[M * 3 * D];
__device__ __half h_h[M * D];
__device__ __half h_ffn1[(size_t)M * FF];
// Half transposed weights: Wh[N][K]
__device__ __half wh_in[NPROJ * D];
__device__ __half wh_c[D * INNER];
__device__ __half wh_mix[D * 3 * D];
__device__ __half wh_1[FF * D];
__device__ __half wh_2[D * FF];

// ---------------------------------------------------------------------------
// Helpers
// ---------------------------------------------------------------------------
__device__ __forceinline__ uint32_t smem_u32(const void* p) {
    uint32_t a;
    asm("{ .reg .u64 t; cvta.to.shared.u64 t, %1; cvt.u32.u64 %0, t; }"
        : "=r"(a) : "l"(p));
    return a;
}
__device__ __forceinline__ void cp_async16(uint32_t dst, const void* src) {
    asm volatile("cp.async.cg.shared.global [%0], [%1], 16;"
                 :: "r"(dst), "l"(src));
}
__device__ __forceinline__ void cp_commit() {
    asm volatile("cp.async.commit_group;" ::: "memory");
}
template <int N>
__device__ __forceinline__ void cp_wait() {
    asm volatile("cp.async.wait_group %0;" :: "n"(N) : "memory");
}
__device__ __forceinline__ void mma_f16(float* c, const uint32_t* a,
                                        const uint32_t* b) {
    asm volatile(
        "mma.sync.aligned.m16n8k16.row.col.f32.f16.f16.f32 "
        "{%0,%1,%2,%3}, {%4,%5,%6,%7}, {%8,%9}, {%0,%1,%2,%3};"
        : "+f"(c[0]), "+f"(c[1]), "+f"(c[2]), "+f"(c[3])
        : "r"(a[0]), "r"(a[1]), "r"(a[2]), "r"(a[3]), "r"(b[0]), "r"(b[1]));
}

// ---------------------------------------------------------------------------
// FP16 mma.sync GEMM: C[M,N] = A[M,K] @ Wh[N,K]^T (+bias, epilogue).
// CTA tile 128x128, BK=32 (2 k16-steps), 8 warps (warp tile 64x32),
// double-buffered cp.async. Smem row stride 40 halfs (conflict-free frags).
// EPI 0: +bias ; EPI 1: gelu(acc+bias) ; EPI 2: (acc+bias+aux)*maskrow
// OutT = float or __half.
// ---------------------------------------------------------------------------
constexpr int STG_B = 128 * 80;                    // bytes per stage (A or B)
constexpr int G_SMEM_BYTES = 4 * STG_B;            // 40960 B

template <int EPI, typename OutT>
__global__ void __launch_bounds__(256, 2)
tc_gemm(const __half* __restrict__ A, int lda,
        const __half* __restrict__ Bh, int ldb,   // Wh[N][K]
        OutT* __restrict__ C, int ldc,
        const float* __restrict__ bias,
        const float* __restrict__ aux, int ldaux,
        const float* __restrict__ mrow,
        int Kk) {
    extern __shared__ char smem[];
    int tid = threadIdx.x, lane = tid & 31, wid = tid >> 5;
    int wm = (wid & 1) * 64, wn = (wid >> 1) * 32;
    int m0 = blockIdx.y * 128, n0 = blockIdx.x * 128;
    int grp = lane >> 2, qid = lane & 3;
    uint32_t sbase = smem_u32(smem);

    float acc[4][4][4];
    #pragma unroll
    for (int a = 0; a < 4; a++)
        #pragma unroll
        for (int b = 0; b < 4; b++)
            #pragma unroll
            for (int c = 0; c < 4; c++) acc[a][b][c] = 0.0f;

    const int KTl = Kk >> 5;

    auto load_tile = [&](int kt, int s) {
        const __half* Ag = A + (size_t)m0 * lda + kt * 32;
        const __half* Bg = Bh + (size_t)n0 * ldb + kt * 32;
        uint32_t abase = sbase + s * STG_B;
        uint32_t bbase = sbase + 2 * STG_B + s * STG_B;
        #pragma unroll
        for (int q = 0; q < 2; q++) {
            int idx = tid + q * 256;
            int row = idx >> 2, seg = idx & 3;   // 4 x 16B per 64B row
            cp_async16(abase + (uint32_t)(row * 80 + seg * 16),
                       Ag + (size_t)row * lda + seg * 8);
            cp_async16(bbase + (uint32_t)(row * 80 + seg * 16),
                       Bg + (size_t)row * ldb + seg * 8);
        }
    };

    load_tile(0, 0);
    cp_commit();

    for (int i = 0; i < KTl; i++) {
        int s = i & 1;
        if (i + 1 < KTl) {
            load_tile(i + 1, s ^ 1);
            cp_commit();
            cp_wait<1>();
        } else {
            cp_wait<0>();
        }
        __syncthreads();
        const __half* Asb = (const __half*)(smem + s * STG_B);
        const __half* Bsb = (const __half*)(smem + 2 * STG_B + s * STG_B);
        #pragma unroll
        for (int ks = 0; ks < 2; ks++) {
            int kb = ks * 16;
            uint32_t af[4][4], bf[4][2];
            #pragma unroll
            for (int mi = 0; mi < 4; mi++) {
                const __half* p = Asb + (wm + mi * 16 + grp) * 40 + kb + qid * 2;
                af[mi][0] = *(const uint32_t*)(p);
                af[mi][1] = *(const uint32_t*)(p + 8 * 40);
                af[mi][2] = *(const uint32_t*)(p + 8);
                af[mi][3] = *(const uint32_t*)(p + 8 * 40 + 8);
            }
            #pragma unroll
            for (int ni = 0; ni < 4; ni++) {
                const __half* p = Bsb + (wn + ni * 8 + grp) * 40 + kb + qid * 2;
                bf[ni][0] = *(const uint32_t*)(p);
                bf[ni][1] = *(const uint32_t*)(p + 8);
            }
            #pragma unroll
            for (int mi = 0; mi < 4; mi++)
                #pragma unroll
                for (int ni = 0; ni < 4; ni++)
                    mma_f16(acc[mi][ni], af[mi], bf[ni]);
        }
        __syncthreads();
    }

    // Epilogue
    #pragma unroll
    for (int mi = 0; mi < 4; mi++) {
        #pragma unroll
        for (int rr = 0; rr < 2; rr++) {
            int row = m0 + wm + mi * 16 + grp + rr * 8;
            float mval = 1.0f;
            if (EPI == 2) mval = mrow[row];
            #pragma unroll
            for (int ni = 0; ni < 4; ni++) {
                int col = n0 + wn + ni * 8 + 2 * qid;
                float x0 = acc[mi][ni][rr * 2 + 0] + bias[col];
                float x1 = acc[mi][ni][rr * 2 + 1] + bias[col + 1];
                if (EPI == 1) {
                    x0 = 0.5f * x0 * (1.0f + erff(x0 * 0.70710678118654752f));
                    x1 = 0.5f * x1 * (1.0f + erff(x1 * 0.70710678118654752f));
                }
                if (EPI == 2) {
                    float2 av = *(const float2*)(aux + (size_t)row * ldaux + col);
                    x0 = (x0 + av.x) * mval;
                    x1 = (x1 + av.y) * mval;
                }
                if constexpr (sizeof(OutT) == 2) {
                    *(__half2*)((__half*)C + (size_t)row * ldc + col) =
                        __floats2half2_rn(x0, x1);
                } else {
                    *(float2*)((float*)C + (size_t)row * ldc + col) =
                        make_float2(x0, x1);
                }
            }
        }
    }
}

// ---------------------------------------------------------------------------
// Weight prep: dst[N][K] = (half) src[K][N]
// ---------------------------------------------------------------------------
__global__ void wprep_kernel(const float* __restrict__ src,
                             __half* __restrict__ dst, int K, int N) {
    __shared__ float tile[32][33];
    int kb = blockIdx.y * 32, nb = blockIdx.x * 32;
    int tx = threadIdx.x, ty = threadIdx.y;
    #pragma unroll
    for (int j = 0; j < 32; j += 8)
        tile[ty + j][tx] = src[(size_t)(kb + ty + j) * N + nb + tx];
    __syncthreads();
    #pragma unroll
    for (int j = 0; j < 32; j += 8)
        dst[(size_t)(nb + ty + j) * K + kb + tx] = __float2half(tile[tx][ty + j]);
}

// ---------------------------------------------------------------------------
// LayerNorm: block per row, 256 threads, half output.
// ---------------------------------------------------------------------------
__global__ void layernorm_kernel(const float* __restrict__ x,
                                 const float* __restrict__ g,
                                 const float* __restrict__ bta,
                                 __half* __restrict__ y) {
    int row = blockIdx.x;
    int tid = threadIdx.x;
    float4 v = ((const float4*)(x + (size_t)row * D))[tid];
    float s = v.x + v.y + v.z + v.w;
    float sq = v.x * v.x + v.y * v.y + v.z * v.z + v.w * v.w;
    __shared__ float ss[256], sv[256];
    ss[tid] = s; sv[tid] = sq;
    __syncthreads();
    #pragma unroll
    for (int o = 128; o; o >>= 1) {
        if (tid < o) { ss[tid] += ss[tid + o]; sv[tid] += sv[tid + o]; }
        __syncthreads();
    }
    float mu = ss[0] * (1.0f / D);
    float var = sv[0] * (1.0f / D) - mu * mu;
    float rstd = rsqrtf(var + 1e-5f);
    int c = tid * 4;
    float4 gv = *(const float4*)(g + c);
    float4 bv = *(const float4*)(bta + c);
    __half2 ha = __floats2half2_rn((v.x - mu) * rstd * gv.x + bv.x,
                                   (v.y - mu) * rstd * gv.y + bv.y);
    __half2 hb = __floats2half2_rn((v.z - mu) * rstd * gv.z + bv.z,
                                   (v.w - mu) * rstd * gv.w + bv.w);
    uint2 st;
    st.x = *(uint32_t*)&ha;
    st.y = *(uint32_t*)&hb;
    *(uint2*)(y + (size_t)row * D + c) = st;
}

// ---------------------------------------------------------------------------
// Causal depthwise conv over time (half in, half out).
// ---------------------------------------------------------------------------
template <int KW>
__global__ void dwconv_kernel(const __half* __restrict__ x,
                              const float* __restrict__ w,
                              const float* __restrict__ bias,
                              __half* __restrict__ y /* pre-offset, stride 3D */) {
    int idx = blockIdx.x * blockDim.x + threadIdx.x;  // over M*D
    int d = idx & (D - 1);
    int bt = idx >> 10;
    int t = bt & (T - 1);
    float acc = bias[d];
    #pragma unroll
    for (int j = 0; j < KW; j++) {
        int tt = t - (KW - 1) + j;
        if (tt >= 0)
            acc += w[d * KW + j] *
                   __half2float(x[((size_t)(bt - (KW - 1) + j)) * D + d]);
    }
    y[(size_t)bt * (3 * D) + d] = __float2half(acc);
}

// ---------------------------------------------------------------------------
// Linear attention, chunked (pass1 -> prefix scan -> parallel pass2).
// ---------------------------------------------------------------------------
__device__ __forceinline__ float elu1(float x) {
    return x > 0.0f ? x + 1.0f : expf(x);
}

__global__ void __launch_bounds__(1024)
attn_pass1(const float* __restrict__ proj, const float* __restrict__ mask,
           float* __restrict__ state) {
    int bh = blockIdx.x / NC, c = blockIdx.x % NC;
    int b = bh / H, h = bh % H;
    int d = threadIdx.x, e = threadIdx.y;
    int tid = e * 32 + d;
    __shared__ float ks[CHUNK][32];
    __shared__ float vs[CHUNK][32];
    int t0 = c * CHUNK;
    for (int i = tid; i < CHUNK * 32; i += 1024) {
        int t = i >> 5, dd = i & 31;
        int rowg = b * T + t0 + t;
        size_t base = (size_t)rowg * NPROJ;
        float m = mask[rowg];
        float kv = proj[base + 1536 + h * 32 + dd];
        ks[t][dd] = elu1(kv) * m;
        vs[t][dd] = proj[base + 2048 + h * 32 + dd] * m;
    }
    __syncthreads();
    float S = 0.0f, kp = 0.0f;
    #pragma unroll 4
    for (int t = 0; t < CHUNK; t++) {
        float kd = ks[t][d];
        S += kd * vs[t][e];
        kp += kd;
    }
    float* st = state + (size_t)blockIdx.x * STATE_STRIDE;
    st[e * 32 + d] = S;
    if (e == 0) st[1024 + d] = kp;
}

__global__ void scan_state(const float* __restrict__ st,
                           float* __restrict__ st2) {
    int bh = blockIdx.x;  // B*H = 32
    for (int i = threadIdx.x; i < STATE_STRIDE; i += blockDim.x) {
        float acc = 0.0f;
        for (int c = 0; c < NC; c++) {
            size_t idx = ((size_t)(bh * NC + c)) * STATE_STRIDE + i;
            st2[idx] = acc;
            acc += st[idx];
        }
    }
}

__global__ void __launch_bounds__(256)
attn_pass2(const float* __restrict__ proj, const float* __restrict__ mask,
           const float* __restrict__ st2, __half* __restrict__ outa) {
    int bh = blockIdx.x / NC, c = blockIdx.x % NC;
    int b = bh / H, h = bh % H;
    int tid = threadIdx.x;
    __shared__ float qs[CHUNK][36];
    __shared__ float ks[CHUNK][36];
    __shared__ float vs[CHUNK][33];
    __shared__ float Aa[CHUNK][CHUNK];
    __shared__ float Ps[32][33];
    __shared__ float kpp[32];
    __shared__ float ms[CHUNK];
    int t0 = c * CHUNK;

    for (int i = tid; i < CHUNK * 32; i += 256) {
        int t = i >> 5, dd = i & 31;
        int rowg = b * T + t0 + t;
        size_t base = (size_t)rowg * NPROJ;
        float m = mask[rowg];
        qs[t][dd] = elu1(proj[base + 1024 + h * 32 + dd]) * m;
        ks[t][dd] = elu1(proj[base + 1536 + h * 32 + dd]) * m;
        vs[t][dd] = proj[base + 2048 + h * 32 + dd] * m;
        if (dd == 0) ms[t] = m;
    }
    const float* stp = st2 + (size_t)blockIdx.x * STATE_STRIDE;
    for (int i = tid; i < 1024; i += 256) {
        int d = i & 31, e = i >> 5;
        Ps[d][e] = stp[i];
    }
    if (tid < 32) kpp[tid] = stp[1024 + tid];
    __syncthreads();

    // A[t][tp] = q[t] . k[tp]
    {
        int ty = tid >> 4, tx = tid & 15;
        int r0 = ty * 4, c0 = tx * 4;
        float a4[4][4] = {};
        #pragma unroll
        for (int d0 = 0; d0 < 32; d0 += 4) {
            float4 qr[4], kr[4];
            #pragma unroll
            for (int i = 0; i < 4; i++)
                qr[i] = *(const float4*)&qs[r0 + i][d0];
            #pragma unroll
            for (int j = 0; j < 4; j++)
                kr[j] = *(const float4*)&ks[c0 + j][d0];
            #pragma unroll
            for (int i = 0; i < 4; i++)
                #pragma unroll
                for (int j = 0; j < 4; j++)
                    a4[i][j] += qr[i].x * kr[j].x + qr[i].y * kr[j].y
                              + qr[i].z * kr[j].z + qr[i].w * kr[j].w;
        }
        #pragma unroll
        for (int i = 0; i < 4; i++)
            #pragma unroll
            for (int j = 0; j < 4; j++)
                Aa[r0 + i][c0 + j] = a4[i][j];
    }
    __syncthreads();

    int w = tid >> 5, e = tid & 31;
    #pragma unroll
    for (int ii = 0; ii < 8; ii++) {
        int t = w + 8 * ii;
        float num = 0.0f, den = 0.0f;
        #pragma unroll
        for (int d = 0; d < 32; d++) {
            float qd = qs[t][d];
            num += qd * Ps[d][e];
            den += qd * kpp[d];
        }
        const float* Arow = Aa[t];
        for (int tp = 0; tp <= t; tp++) {
            float a = Arow[tp];
            num += a * vs[tp][e];
            den += a;
        }
        outa[(size_t)(b * T + t0 + t) * INNER + h * 32 + e] =
            __float2half(num / (den + 1e-6f) * ms[t]);
    }
}

// ---------------------------------------------------------------------------
// Fused gate + LN2: out1 = (inputs + sigmoid(gate)*mixed)*mask (fp32),
// hb = layernorm(out1) (half). Block per row.
// ---------------------------------------------------------------------------
__global__ void gate_ln2(const float* __restrict__ inp,
                         const float* __restrict__ proj,
                         const float* __restrict__ mixed,
                         const float* __restrict__ mask,
                         const float* __restrict__ g,
                         const float* __restrict__ bta,
                         float* __restrict__ out1,
                         __half* __restrict__ hb) {
    int row = blockIdx.x;
    int tid = threadIdx.x;
    int c = tid * 4;
    float mk = mask[row];
    float4 iv = ((const float4*)(inp + (size_t)row * D))[tid];
    float4 mv = ((const float4*)(mixed + (size_t)row * D))[tid];
    float4 gt = *(const float4*)(proj + (size_t)row * NPROJ + c);
    float4 o;
    o.x = (iv.x + mv.x / (1.0f + expf(-gt.x))) * mk;
    o.y = (iv.y + mv.y / (1.0f + expf(-gt.y))) * mk;
    o.z = (iv.z + mv.z / (1.0f + expf(-gt.z))) * mk;
    o.w = (iv.w + mv.w / (1.0f + expf(-gt.w))) * mk;
    ((float4*)(out1 + (size_t)row * D))[tid] = o;

    float s = o.x + o.y + o.z + o.w;
    float sq = o.x * o.x + o.y * o.y + o.z * o.z + o.w * o.w;
    __shared__ float ss[256], sv[256];
    ss[tid] = s; sv[tid] = sq;
    __syncthreads();
    #pragma unroll
    for (int of = 128; of; of >>= 1) {
        if (tid < of) { ss[tid] += ss[tid + of]; sv[tid] += sv[tid + of]; }
        __syncthreads();
    }
    float mu = ss[0] * (1.0f / D);
    float var = sv[0] * (1.0f / D) - mu * mu;
    float rstd = rsqrtf(var + 1e-5f);
    float4 gv = *(const float4*)(g + c);
    float4 bv = *(const float4*)(bta + c);
    __half2 ha = __floats2half2_rn((o.x - mu) * rstd * gv.x + bv.x,
                                   (o.y - mu) * rstd * gv.y + bv.y);
    __half2 hb2 = __floats2half2_rn((o.z - mu) * rstd * gv.z + bv.z,
                                    (o.w - mu) * rstd * gv.w + bv.w);
    uint2 st;
    st.x = *(uint32_t*)&ha;
    st.y = *(uint32_t*)&hb2;
    *(uint2*)(hb + (size_t)row * D + c) = st;
}

// ---------------------------------------------------------------------------
// Launch
// ---------------------------------------------------------------------------
extern "C" void kernel_launch(void* const* d_in, const int* in_sizes, int n_in,
                              void* d_out, int out_size) {
    const float* inputs = (const float*)d_in[0];
    const float* mask   = (const float*)d_in[1];
    const float* ln1_g  = (const float*)d_in[2];
    const float* ln1_b  = (const float*)d_in[3];
    const float* W_in   = (const float*)d_in[4];
    const float* b_in   = (const float*)d_in[5];
    const float* W_c    = (const float*)d_in[6];
    const float* b_c    = (const float*)d_in[7];
    const float* w_t    = (const float*)d_in[8];
    const float* b_t    = (const float*)d_in[9];
    const float* w_p    = (const float*)d_in[10];
    const float* b_p    = (const float*)d_in[11];
    const float* W_mix  = (const float*)d_in[12];
    const float* b_mix  = (const float*)d_in[13];
    const float* ln2_g  = (const float*)d_in[14];
    const float* ln2_b  = (const float*)d_in[15];
    const float* W1     = (const float*)d_in[16];
    const float* b1     = (const float*)d_in[17];
    const float* W2     = (const float*)d_in[18];
    const float* b2     = (const float*)d_in[19];
    float* out = (float*)d_out;

    float *proj, *mixed, *out1, *state, *state2;
    __half *normedh, *attnh, *cath, *hh, *ffn1h;
    __half *win, *wc, *wmix, *w1, *w2;
    cudaGetSymbolAddress((void**)&proj,   g_proj);
    cudaGetSymbolAddress((void**)&mixed,  g_mixed);
    cudaGetSymbolAddress((void**)&out1,   g_out1);
    cudaGetSymbolAddress((void**)&state,  g_state);
    cudaGetSymbolAddress((void**)&state2, g_state2);
    cudaGetSymbolAddress((void**)&normedh, h_normed);
    cudaGetSymbolAddress((void**)&attnh,   h_attn);
    cudaGetSymbolAddress((void**)&cath,    h_cat);
    cudaGetSymbolAddress((void**)&hh,      h_h);
    cudaGetSymbolAddress((void**)&ffn1h,   h_ffn1);
    cudaGetSymbolAddress((void**)&win,  wh_in);
    cudaGetSymbolAddress((void**)&wc,   wh_c);
    cudaGetSymbolAddress((void**)&wmix, wh_mix);
    cudaGetSymbolAddress((void**)&w1,   wh_1);
    cudaGetSymbolAddress((void**)&w2,   wh_2);

    // Weight prep (transpose + fp16)
    dim3 tb(32, 8);
    wprep_kernel<<<dim3(NPROJ / 32, D / 32), tb>>>(W_in, win, D, NPROJ);
    wprep_kernel<<<dim3(D / 32, INNER / 32), tb>>>(W_c, wc, INNER, D);
    wprep_kernel<<<dim3(D / 32, (3 * D) / 32), tb>>>(W_mix, wmix, 3 * D, D);
    wprep_kernel<<<dim3(FF / 32, D / 32), tb>>>(W1, w1, D, FF);
    wprep_kernel<<<dim3(D / 32, FF / 32), tb>>>(W2, w2, FF, D);

    // 1. LN1 -> half
    layernorm_kernel<<<M, 256>>>(inputs, ln1_g, ln1_b, normedh);

    // 2. proj = normed @ W_in + b_in (fp32 out)
    tc_gemm<0, float><<<dim3(NPROJ / 128, M / 128), 256, G_SMEM_BYTES>>>(
        normedh, D, win, D, proj, NPROJ, b_in, nullptr, 0, nullptr, D);

    // 3. linear attention
    attn_pass1<<<B * H * NC, dim3(32, 32)>>>(proj, mask, state);
    scan_state<<<B * H, 1024>>>(state, state2);
    attn_pass2<<<B * H * NC, 256>>>(proj, mask, state2, attnh);

    // 4. content = attn @ W_c + b_c -> cat[:, 0:D] (half)
    tc_gemm<0, __half><<<dim3(D / 128, M / 128), 256, G_SMEM_BYTES>>>(
        attnh, INNER, wc, INNER, cath, 3 * D, b_c, nullptr, 0, nullptr, INNER);

    // 5. dwconvs -> cat[:, D:2D] and cat[:, 2D:3D]
    dwconv_kernel<KT><<<(M * D) / 256, 256>>>(normedh, w_t, b_t, cath + D);
    dwconv_kernel<KP><<<(M * D) / 256, 256>>>(normedh, w_p, b_p, cath + 2 * D);

    // 6. mixed = cat @ W_mix + b_mix (fp32 out)
    tc_gemm<0, float><<<dim3(D / 128, M / 128), 256, G_SMEM_BYTES>>>(
        cath, 3 * D, wmix, 3 * D, mixed, D, b_mix, nullptr, 0, nullptr, 3 * D);

    // 7+8. fused gate + LN2
    gate_ln2<<<M, 256>>>(inputs, proj, mixed, mask, ln2_g, ln2_b, out1, hh);

    // 9. ffn1 = gelu(h @ W1 + b1) (half out)
    tc_gemm<1, __half><<<dim3(FF / 128, M / 128), 256, G_SMEM_BYTES>>>(
        hh, D, w1, D, ffn1h, FF, b1, nullptr, 0, nullptr, D);

    // 10. out = (out1 + ffn1 @ W2 + b2) * mask (fp32 out)
    tc_gemm<2, float><<<dim3(D / 128, M / 128), 256, G_SMEM_BYTES>>>(
        ffn1h, FF, w2, FF, out, D, b2, out1, D, mask, FF);
}

// round 7
// speedup vs baseline: 4.7606x; 1.0180x over previous
#include <cuda_runtime.h>
#include <cuda_fp16.h>
#include <math.h>
#include <stdint.h>

// Problem constants
constexpr int B = 2, T = 2048, D = 1024, H = 16, HD = 32, INNER = 512, FF = 4096;
constexpr int M = B * T;              // 4096 rows
constexpr int NPROJ = D + 3 * INNER;  // 2560
constexpr int KT = 3, KP = 15;
constexpr int CHUNK = 64, NC = T / CHUNK;   // 32 chunks
constexpr int STATE_STRIDE = HD * HD + HD;  // 1056 floats per (bh, chunk)

// Scratch (allocations are forbidden -> __device__ globals)
__device__ float g_proj[M * NPROJ];
__device__ float g_mixed[M * D];
__device__ float g_out1[M * D];
__device__ float g_state[B * H * NC * STATE_STRIDE];
__device__ float g_state2[B * H * NC * STATE_STRIDE];
// Half activations (GEMM A operands)
__device__ __half h_normed[M * D];
__device__ __half h_attn[M * INNER];
__device__ __half h_cat[M * 3 * D];
__device__ __half h_h[M * D];
__device__ __half h_ffn1[(size_t)M * FF];
// Half transposed weights: Wh[N][K]
__device__ __half wh_in[NPROJ * D];
__device__ __half wh_c[D * INNER];
__device__ __half wh_mix[D * 3 * D];
__device__ __half wh_1[FF * D];
__device__ __half wh_2[D * FF];

// ---------------------------------------------------------------------------
// Helpers
// ---------------------------------------------------------------------------
__device__ __forceinline__ uint32_t smem_u32(const void* p) {
    uint32_t a;
    asm("{ .reg .u64 t; cvta.to.shared.u64 t, %1; cvt.u32.u64 %0, t; }"
        : "=r"(a) : "l"(p));
    return a;
}
__device__ __forceinline__ void cp_async16(uint32_t dst, const void* src) {
    asm volatile("cp.async.cg.shared.global [%0], [%1], 16;"
                 :: "r"(dst), "l"(src));
}
__device__ __forceinline__ void cp_commit() {
    asm volatile("cp.async.commit_group;" ::: "memory");
}
template <int N>
__device__ __forceinline__ void cp_wait() {
    asm volatile("cp.async.wait_group %0;" :: "n"(N) : "memory");
}
__device__ __forceinline__ void mma_f16(float* c, const uint32_t* a,
                                        const uint32_t* b) {
    asm volatile(
        "mma.sync.aligned.m16n8k16.row.col.f32.f16.f16.f32 "
        "{%0,%1,%2,%3}, {%4,%5,%6,%7}, {%8,%9}, {%0,%1,%2,%3};"
        : "+f"(c[0]), "+f"(c[1]), "+f"(c[2]), "+f"(c[3])
        : "r"(a[0]), "r"(a[1]), "r"(a[2]), "r"(a[3]), "r"(b[0]), "r"(b[1]));
}

// ---------------------------------------------------------------------------
// FP16 mma.sync GEMM: C[M,N] = A[M,K] @ Wh[N,K]^T (+bias, epilogue).
// CTA tile 128x128, BK=32 (2 k16-steps), 8 warps (warp tile 64x32),
// 3-stage cp.async pipeline. Smem row stride 40 halfs (conflict-free frags).
// EPI 0: +bias ; EPI 1: gelu(acc+bias) ; EPI 2: (acc+bias+aux)*maskrow
// ---------------------------------------------------------------------------
constexpr int STG_B = 128 * 80;                    // bytes per stage (A or B)
constexpr int G_NSTG = 3;
constexpr int G_SMEM_BYTES = 2 * G_NSTG * STG_B;   // 61440 B

template <int EPI, typename OutT>
__global__ void __launch_bounds__(256, 2)
tc_gemm(const __half* __restrict__ A, int lda,
        const __half* __restrict__ Bh, int ldb,   // Wh[N][K]
        OutT* __restrict__ C, int ldc,
        const float* __restrict__ bias,
        const float* __restrict__ aux, int ldaux,
        const float* __restrict__ mrow,
        int Kk) {
    extern __shared__ char smem[];
    int tid = threadIdx.x, lane = tid & 31, wid = tid >> 5;
    int wm = (wid & 1) * 64, wn = (wid >> 1) * 32;
    int m0 = blockIdx.y * 128, n0 = blockIdx.x * 128;
    int grp = lane >> 2, qid = lane & 3;
    uint32_t sbase = smem_u32(smem);

    float acc[4][4][4];
    #pragma unroll
    for (int a = 0; a < 4; a++)
        #pragma unroll
        for (int b = 0; b < 4; b++)
            #pragma unroll
            for (int c = 0; c < 4; c++) acc[a][b][c] = 0.0f;

    const int KTl = Kk >> 5;

    auto load_tile = [&](int kt, int s) {
        const __half* Ag = A + (size_t)m0 * lda + kt * 32;
        const __half* Bg = Bh + (size_t)n0 * ldb + kt * 32;
        uint32_t abase = sbase + s * STG_B;
        uint32_t bbase = sbase + G_NSTG * STG_B + s * STG_B;
        #pragma unroll
        for (int q = 0; q < 2; q++) {
            int idx = tid + q * 256;
            int row = idx >> 2, seg = idx & 3;   // 4 x 16B per 64B row
            cp_async16(abase + (uint32_t)(row * 80 + seg * 16),
                       Ag + (size_t)row * lda + seg * 8);
            cp_async16(bbase + (uint32_t)(row * 80 + seg * 16),
                       Bg + (size_t)row * ldb + seg * 8);
        }
    };

    // prologue: stages 0,1
    load_tile(0, 0);
    cp_commit();
    if (KTl > 1) load_tile(1, 1);
    cp_commit();

    for (int i = 0; i < KTl; i++) {
        int s = i % G_NSTG;
        // issue loads for iter i+2 into the stage freed by compute i-1
        {
            int li = i + 2;
            if (li < KTl) load_tile(li, li % G_NSTG);
            cp_commit();
        }
        cp_wait<2>();   // loads of iter i complete
        __syncthreads();
        const __half* Asb = (const __half*)(smem + s * STG_B);
        const __half* Bsb = (const __half*)(smem + G_NSTG * STG_B + s * STG_B);
        #pragma unroll
        for (int ks = 0; ks < 2; ks++) {
            int kb = ks * 16;
            uint32_t af[4][4], bf[4][2];
            #pragma unroll
            for (int mi = 0; mi < 4; mi++) {
                const __half* p = Asb + (wm + mi * 16 + grp) * 40 + kb + qid * 2;
                af[mi][0] = *(const uint32_t*)(p);
                af[mi][1] = *(const uint32_t*)(p + 8 * 40);
                af[mi][2] = *(const uint32_t*)(p + 8);
                af[mi][3] = *(const uint32_t*)(p + 8 * 40 + 8);
            }
            #pragma unroll
            for (int ni = 0; ni < 4; ni++) {
                const __half* p = Bsb + (wn + ni * 8 + grp) * 40 + kb + qid * 2;
                bf[ni][0] = *(const uint32_t*)(p);
                bf[ni][1] = *(const uint32_t*)(p + 8);
            }
            #pragma unroll
            for (int mi = 0; mi < 4; mi++)
                #pragma unroll
                for (int ni = 0; ni < 4; ni++)
                    mma_f16(acc[mi][ni], af[mi], bf[ni]);
        }
        __syncthreads();
    }

    // Epilogue
    #pragma unroll
    for (int mi = 0; mi < 4; mi++) {
        #pragma unroll
        for (int rr = 0; rr < 2; rr++) {
            int row = m0 + wm + mi * 16 + grp + rr * 8;
            float mval = 1.0f;
            if (EPI == 2) mval = mrow[row];
            #pragma unroll
            for (int ni = 0; ni < 4; ni++) {
                int col = n0 + wn + ni * 8 + 2 * qid;
                float x0 = acc[mi][ni][rr * 2 + 0] + bias[col];
                float x1 = acc[mi][ni][rr * 2 + 1] + bias[col + 1];
                if (EPI == 1) {
                    x0 = 0.5f * x0 * (1.0f + erff(x0 * 0.70710678118654752f));
                    x1 = 0.5f * x1 * (1.0f + erff(x1 * 0.70710678118654752f));
                }
                if (EPI == 2) {
                    float2 av = *(const float2*)(aux + (size_t)row * ldaux + col);
                    x0 = (x0 + av.x) * mval;
                    x1 = (x1 + av.y) * mval;
                }
                if constexpr (sizeof(OutT) == 2) {
                    *(__half2*)((__half*)C + (size_t)row * ldc + col) =
                        __floats2half2_rn(x0, x1);
                } else {
                    *(float2*)((float*)C + (size_t)row * ldc + col) =
                        make_float2(x0, x1);
                }
            }
        }
    }
}

// ---------------------------------------------------------------------------
// Weight prep: dst[N][K] = (half) src[K][N]. Tile 64(K) x 32(N).
// Coalesced float loads, coalesced half2 stores.
// ---------------------------------------------------------------------------
__global__ void __launch_bounds__(256)
wprep_kernel(const float* __restrict__ src, __half* __restrict__ dst,
             int K, int N) {
    __shared__ float tile[64][33];
    int kb = blockIdx.y * 64, nb = blockIdx.x * 32;
    int tid = threadIdx.x;
    #pragma unroll
    for (int q = 0; q < 8; q++) {
        int idx = tid + q * 256;
        int row = idx >> 5, col = idx & 31;
        tile[row][col] = src[(size_t)(kb + row) * N + nb + col];
    }
    __syncthreads();
    #pragma unroll
    for (int q = 0; q < 4; q++) {
        int idx = tid + q * 256;
        int n = idx >> 5, kk = idx & 31;
        __half2 hv = __floats2half2_rn(tile[2 * kk][n], tile[2 * kk + 1][n]);
        *(__half2*)(dst + (size_t)(nb + n) * K + kb + 2 * kk) = hv;
    }
}

// ---------------------------------------------------------------------------
// LayerNorm: block per row, 256 threads, half output.
// ---------------------------------------------------------------------------
__global__ void layernorm_kernel(const float* __restrict__ x,
                                 const float* __restrict__ g,
                                 const float* __restrict__ bta,
                                 __half* __restrict__ y) {
    int row = blockIdx.x;
    int tid = threadIdx.x;
    float4 v = ((const float4*)(x + (size_t)row * D))[tid];
    float s = v.x + v.y + v.z + v.w;
    float sq = v.x * v.x + v.y * v.y + v.z * v.z + v.w * v.w;
    __shared__ float ss[256], sv[256];
    ss[tid] = s; sv[tid] = sq;
    __syncthreads();
    #pragma unroll
    for (int o = 128; o; o >>= 1) {
        if (tid < o) { ss[tid] += ss[tid + o]; sv[tid] += sv[tid + o]; }
        __syncthreads();
    }
    float mu = ss[0] * (1.0f / D);
    float var = sv[0] * (1.0f / D) - mu * mu;
    float rstd = rsqrtf(var + 1e-5f);
    int c = tid * 4;
    float4 gv = *(const float4*)(g + c);
    float4 bv = *(const float4*)(bta + c);
    __half2 ha = __floats2half2_rn((v.x - mu) * rstd * gv.x + bv.x,
                                   (v.y - mu) * rstd * gv.y + bv.y);
    __half2 hb = __floats2half2_rn((v.z - mu) * rstd * gv.z + bv.z,
                                   (v.w - mu) * rstd * gv.w + bv.w);
    uint2 st;
    st.x = *(uint32_t*)&ha;
    st.y = *(uint32_t*)&hb;
    *(uint2*)(y + (size_t)row * D + c) = st;
}

// ---------------------------------------------------------------------------
// Causal depthwise conv over time, half2-vectorized over channels.
// ---------------------------------------------------------------------------
template <int KW>
__global__ void dwconv_kernel(const __half* __restrict__ x,
                              const float* __restrict__ w,
                              const float* __restrict__ bias,
                              __half* __restrict__ y /* pre-offset, stride 3D */) {
    int idx = blockIdx.x * blockDim.x + threadIdx.x;  // over M*D/2
    int d2 = idx & (D / 2 - 1);
    int d = d2 * 2;
    int bt = idx >> 9;
    int t = bt & (T - 1);
    float a0 = bias[d], a1 = bias[d + 1];
    #pragma unroll
    for (int j = 0; j < KW; j++) {
        int tt = t - (KW - 1) + j;
        if (tt >= 0) {
            __half2 xv = *(const __half2*)(x + ((size_t)(bt - (KW - 1) + j)) * D + d);
            float2 xf = __half22float2(xv);
            a0 += w[d * KW + j] * xf.x;
            a1 += w[(d + 1) * KW + j] * xf.y;
        }
    }
    *(__half2*)(y + (size_t)bt * (3 * D) + d) = __floats2half2_rn(a0, a1);
}

// ---------------------------------------------------------------------------
// Linear attention, chunked (pass1 -> prefix scan -> parallel pass2).
// ---------------------------------------------------------------------------
__device__ __forceinline__ float elu1(float x) {
    return x > 0.0f ? x + 1.0f : expf(x);
}

__global__ void __launch_bounds__(1024)
attn_pass1(const float* __restrict__ proj, const float* __restrict__ mask,
           float* __restrict__ state) {
    int bh = blockIdx.x / NC, c = blockIdx.x % NC;
    int b = bh / H, h = bh % H;
    int d = threadIdx.x, e = threadIdx.y;
    int tid = e * 32 + d;
    __shared__ float ks[CHUNK][32];
    __shared__ float vs[CHUNK][32];
    int t0 = c * CHUNK;
    for (int i = tid; i < CHUNK * 32; i += 1024) {
        int t = i >> 5, dd = i & 31;
        int rowg = b * T + t0 + t;
        size_t base = (size_t)rowg * NPROJ;
        float m = mask[rowg];
        float kv = proj[base + 1536 + h * 32 + dd];
        ks[t][dd] = elu1(kv) * m;
        vs[t][dd] = proj[base + 2048 + h * 32 + dd] * m;
    }
    __syncthreads();
    float S = 0.0f, kp = 0.0f;
    #pragma unroll 4
    for (int t = 0; t < CHUNK; t++) {
        float kd = ks[t][d];
        S += kd * vs[t][e];
        kp += kd;
    }
    float* st = state + (size_t)blockIdx.x * STATE_STRIDE;
    st[e * 32 + d] = S;
    if (e == 0) st[1024 + d] = kp;
}

// Exclusive prefix over chunks, 8-way sliced for latency hiding.
__global__ void scan_state(const float* __restrict__ st,
                           float* __restrict__ st2) {
    int bh = blockIdx.x;                       // 32
    int i = blockIdx.y * 132 + threadIdx.x;    // 8 slices x 132
    if (i >= STATE_STRIDE) return;
    float acc = 0.0f;
    for (int c = 0; c < NC; c++) {
        size_t idx = ((size_t)(bh * NC + c)) * STATE_STRIDE + i;
        st2[idx] = acc;
        acc += st[idx];
    }
}

__global__ void __launch_bounds__(256)
attn_pass2(const float* __restrict__ proj, const float* __restrict__ mask,
           const float* __restrict__ st2, __half* __restrict__ outa) {
    int bh = blockIdx.x / NC, c = blockIdx.x % NC;
    int b = bh / H, h = bh % H;
    int tid = threadIdx.x;
    __shared__ float qs[CHUNK][36];
    __shared__ float ks[CHUNK][36];
    __shared__ float vs[CHUNK][33];
    __shared__ float Aa[CHUNK][CHUNK];
    __shared__ float Ps[32][33];
    __shared__ float kpp[32];
    __shared__ float ms[CHUNK];
    int t0 = c * CHUNK;

    for (int i = tid; i < CHUNK * 32; i += 256) {
        int t = i >> 5, dd = i & 31;
        int rowg = b * T + t0 + t;
        size_t base = (size_t)rowg * NPROJ;
        float m = mask[rowg];
        qs[t][dd] = elu1(proj[base + 1024 + h * 32 + dd]) * m;
        ks[t][dd] = elu1(proj[base + 1536 + h * 32 + dd]) * m;
        vs[t][dd] = proj[base + 2048 + h * 32 + dd] * m;
        if (dd == 0) ms[t] = m;
    }
    const float* stp = st2 + (size_t)blockIdx.x * STATE_STRIDE;
    for (int i = tid; i < 1024; i += 256) {
        int d = i & 31, e = i >> 5;
        Ps[d][e] = stp[i];
    }
    if (tid < 32) kpp[tid] = stp[1024 + tid];
    __syncthreads();

    // A[t][tp] = q[t] . k[tp]
    {
        int ty = tid >> 4, tx = tid & 15;
        int r0 = ty * 4, c0 = tx * 4;
        float a4[4][4] = {};
        #pragma unroll
        for (int d0 = 0; d0 < 32; d0 += 4) {
            float4 qr[4], kr[4];
            #pragma unroll
            for (int i = 0; i < 4; i++)
                qr[i] = *(const float4*)&qs[r0 + i][d0];
            #pragma unroll
            for (int j = 0; j < 4; j++)
                kr[j] = *(const float4*)&ks[c0 + j][d0];
            #pragma unroll
            for (int i = 0; i < 4; i++)
                #pragma unroll
                for (int j = 0; j < 4; j++)
                    a4[i][j] += qr[i].x * kr[j].x + qr[i].y * kr[j].y
                              + qr[i].z * kr[j].z + qr[i].w * kr[j].w;
        }
        #pragma unroll
        for (int i = 0; i < 4; i++)
            #pragma unroll
            for (int j = 0; j < 4; j++)
                Aa[r0 + i][c0 + j] = a4[i][j];
    }
    __syncthreads();

    int w = tid >> 5, e = tid & 31;
    #pragma unroll
    for (int ii = 0; ii < 8; ii++) {
        int t = w + 8 * ii;
        float num = 0.0f, den = 0.0f;
        #pragma unroll
        for (int d = 0; d < 32; d++) {
            float qd = qs[t][d];
            num += qd * Ps[d][e];
            den += qd * kpp[d];
        }
        const float* Arow = Aa[t];
        for (int tp = 0; tp <= t; tp++) {
            float a = Arow[tp];
            num += a * vs[tp][e];
            den += a;
        }
        outa[(size_t)(b * T + t0 + t) * INNER + h * 32 + e] =
            __float2half(num / (den + 1e-6f) * ms[t]);
    }
}

// ---------------------------------------------------------------------------
// Fused gate + LN2
// ---------------------------------------------------------------------------
__global__ void gate_ln2(const float* __restrict__ inp,
                         const float* __restrict__ proj,
                         const float* __restrict__ mixed,
                         const float* __restrict__ mask,
                         const float* __restrict__ g,
                         const float* __restrict__ bta,
                         float* __restrict__ out1,
                         __half* __restrict__ hb) {
    int row = blockIdx.x;
    int tid = threadIdx.x;
    int c = tid * 4;
    float mk = mask[row];
    float4 iv = ((const float4*)(inp + (size_t)row * D))[tid];
    float4 mv = ((const float4*)(mixed + (size_t)row * D))[tid];
    float4 gt = *(const float4*)(proj + (size_t)row * NPROJ + c);
    float4 o;
    o.x = (iv.x + mv.x / (1.0f + expf(-gt.x))) * mk;
    o.y = (iv.y + mv.y / (1.0f + expf(-gt.y))) * mk;
    o.z = (iv.z + mv.z / (1.0f + expf(-gt.z))) * mk;
    o.w = (iv.w + mv.w / (1.0f + expf(-gt.w))) * mk;
    ((float4*)(out1 + (size_t)row * D))[tid] = o;

    float s = o.x + o.y + o.z + o.w;
    float sq = o.x * o.x + o.y * o.y + o.z * o.z + o.w * o.w;
    __shared__ float ss[256], sv[256];
    ss[tid] = s; sv[tid] = sq;
    __syncthreads();
    #pragma unroll
    for (int of = 128; of; of >>= 1) {
        if (tid < of) { ss[tid] += ss[tid + of]; sv[tid] += sv[tid + of]; }
        __syncthreads();
    }
    float mu = ss[0] * (1.0f / D);
    float var = sv[0] * (1.0f / D) - mu * mu;
    float rstd = rsqrtf(var + 1e-5f);
    float4 gv = *(const float4*)(g + c);
    float4 bv = *(const float4*)(bta + c);
    __half2 ha = __floats2half2_rn((o.x - mu) * rstd * gv.x + bv.x,
                                   (o.y - mu) * rstd * gv.y + bv.y);
    __half2 hb2 = __floats2half2_rn((o.z - mu) * rstd * gv.z + bv.z,
                                    (o.w - mu) * rstd * gv.w + bv.w);
    uint2 st;
    st.x = *(uint32_t*)&ha;
    st.y = *(uint32_t*)&hb2;
    *(uint2*)(hb + (size_t)row * D + c) = st;
}

// ---------------------------------------------------------------------------
// Launch
// ---------------------------------------------------------------------------
extern "C" void kernel_launch(void* const* d_in, const int* in_sizes, int n_in,
                              void* d_out, int out_size) {
    const float* inputs = (const float*)d_in[0];
    const float* mask   = (const float*)d_in[1];
    const float* ln1_g  = (const float*)d_in[2];
    const float* ln1_b  = (const float*)d_in[3];
    const float* W_in   = (const float*)d_in[4];
    const float* b_in   = (const float*)d_in[5];
    const float* W_c    = (const float*)d_in[6];
    const float* b_c    = (const float*)d_in[7];
    const float* w_t    = (const float*)d_in[8];
    const float* b_t    = (const float*)d_in[9];
    const float* w_p    = (const float*)d_in[10];
    const float* b_p    = (const float*)d_in[11];
    const float* W_mix  = (const float*)d_in[12];
    const float* b_mix  = (const float*)d_in[13];
    const float* ln2_g  = (const float*)d_in[14];
    const float* ln2_b  = (const float*)d_in[15];
    const float* W1     = (const float*)d_in[16];
    const float* b1     = (const float*)d_in[17];
    const float* W2     = (const float*)d_in[18];
    const float* b2     = (const float*)d_in[19];
    float* out = (float*)d_out;

    float *proj, *mixed, *out1, *state, *state2;
    __half *normedh, *attnh, *cath, *hh, *ffn1h;
    __half *win, *wc, *wmix, *w1, *w2;
    cudaGetSymbolAddress((void**)&proj,   g_proj);
    cudaGetSymbolAddress((void**)&mixed,  g_mixed);
    cudaGetSymbolAddress((void**)&out1,   g_out1);
    cudaGetSymbolAddress((void**)&state,  g_state);
    cudaGetSymbolAddress((void**)&state2, g_state2);
    cudaGetSymbolAddress((void**)&normedh, h_normed);
    cudaGetSymbolAddress((void**)&attnh,   h_attn);
    cudaGetSymbolAddress((void**)&cath,    h_cat);
    cudaGetSymbolAddress((void**)&hh,      h_h);
    cudaGetSymbolAddress((void**)&ffn1h,   h_ffn1);
    cudaGetSymbolAddress((void**)&win,  wh_in);
    cudaGetSymbolAddress((void**)&wc,   wh_c);
    cudaGetSymbolAddress((void**)&wmix, wh_mix);
    cudaGetSymbolAddress((void**)&w1,   wh_1);
    cudaGetSymbolAddress((void**)&w2,   wh_2);

    // Raise dynamic smem limit for the 3-stage GEMM (61440 B > 48 KB default).
    cudaFuncSetAttribute(tc_gemm<0, float>,
                         cudaFuncAttributeMaxDynamicSharedMemorySize, G_SMEM_BYTES);
    cudaFuncSetAttribute(tc_gemm<0, __half>,
                         cudaFuncAttributeMaxDynamicSharedMemorySize, G_SMEM_BYTES);
    cudaFuncSetAttribute(tc_gemm<1, __half>,
                         cudaFuncAttributeMaxDynamicSharedMemorySize, G_SMEM_BYTES);
    cudaFuncSetAttribute(tc_gemm<2, float>,
                         cudaFuncAttributeMaxDynamicSharedMemorySize, G_SMEM_BYTES);

    // Weight prep (transpose + fp16)
    wprep_kernel<<<dim3(NPROJ / 32, D / 64), 256>>>(W_in, win, D, NPROJ);
    wprep_kernel<<<dim3(D / 32, INNER / 64), 256>>>(W_c, wc, INNER, D);
    wprep_kernel<<<dim3(D / 32, (3 * D) / 64), 256>>>(W_mix, wmix, 3 * D, D);
    wprep_kernel<<<dim3(FF / 32, D / 64), 256>>>(W1, w1, D, FF);
    wprep_kernel<<<dim3(D / 32, FF / 64), 256>>>(W2, w2, FF, D);

    // 1. LN1 -> half
    layernorm_kernel<<<M, 256>>>(inputs, ln1_g, ln1_b, normedh);

    // 2. proj = normed @ W_in + b_in (fp32 out)
    tc_gemm<0, float><<<dim3(NPROJ / 128, M / 128), 256, G_SMEM_BYTES>>>(
        normedh, D, win, D, proj, NPROJ, b_in, nullptr, 0, nullptr, D);

    // 3. linear attention
    attn_pass1<<<B * H * NC, dim3(32, 32)>>>(proj, mask, state);
    scan_state<<<dim3(B * H, 8), 132>>>(state, state2);
    attn_pass2<<<B * H * NC, 256>>>(proj, mask, state2, attnh);

    // 4. content = attn @ W_c + b_c -> cat[:, 0:D] (half)
    tc_gemm<0, __half><<<dim3(D / 128, M / 128), 256, G_SMEM_BYTES>>>(
        attnh, INNER, wc, INNER, cath, 3 * D, b_c, nullptr, 0, nullptr, INNER);

    // 5. dwconvs -> cat[:, D:2D] and cat[:, 2D:3D]
    dwconv_kernel<KT><<<(M * D / 2) / 256, 256>>>(normedh, w_t, b_t, cath + D);
    dwconv_kernel<KP><<<(M * D / 2) / 256, 256>>>(normedh, w_p, b_p, cath + 2 * D);

    // 6. mixed = cat @ W_mix + b_mix (fp32 out)
    tc_gemm<0, float><<<dim3(D / 128, M / 128), 256, G_SMEM_BYTES>>>(
        cath, 3 * D, wmix, 3 * D, mixed, D, b_mix, nullptr, 0, nullptr, 3 * D);

    // 7+8. fused gate + LN2
    gate_ln2<<<M, 256>>>(inputs, proj, mixed, mask, ln2_g, ln2_b, out1, hh);

    // 9. ffn1 = gelu(h @ W1 + b1) (half out)
    tc_gemm<1, __half><<<dim3(FF / 128, M / 128), 256, G_SMEM_BYTES>>>(
        hh, D, w1, D, ffn1h, FF, b1, nullptr, 0, nullptr, D);

    // 10. out = (out1 + ffn1 @ W2 + b2) * mask (fp32 out)
    tc_gemm<2, float><<<dim3(D / 128, M / 128), 256, G_SMEM_BYTES>>>(
        ffn1h, FF, w2, FF, out, D, b2, out1, D, mask, FF);
}

// round 8
// speedup vs baseline: 5.3953x; 1.1333x over previous
#include <cuda_runtime.h>
#include <cuda_fp16.h>
#include <math.h>
#include <stdint.h>

// Problem constants
constexpr int B = 2, T = 2048, D = 1024, H = 16, HD = 32, INNER = 512, FF = 4096;
constexpr int M = B * T;              // 4096 rows
constexpr int NPROJ = D + 3 * INNER;  // 2560
constexpr int KT = 3, KP = 15;
constexpr int CHUNK = 64, NC = T / CHUNK;   // 32 chunks
constexpr int STATE_STRIDE = HD * HD + HD;  // 1056 floats per (bh, chunk)

// Scratch (allocations are forbidden -> __device__ globals)
__device__ float g_proj[M * NPROJ];
__device__ float g_mixed[M * D];
__device__ float g_out1[M * D];
__device__ float g_state[B * H * NC * STATE_STRIDE];
__device__ float g_state2[B * H * NC * STATE_STRIDE];
// Half activations (GEMM A operands)
__device__ __half h_normed[M * D];
__device__ __half h_attn[M * INNER];
__device__ __half h_cat[M * 3 * D];
__device__ __half h_h[M * D];
__device__ __half h_ffn1[(size_t)M * FF];
// Half transposed weights: Wh[N][K]
__device__ __half wh_in[NPROJ * D];
__device__ __half wh_c[D * INNER];
__device__ __half wh_mix[D * 3 * D];
__device__ __half wh_1[FF * D];
__device__ __half wh_2[D * FF];

// ---------------------------------------------------------------------------
// Helpers
// ---------------------------------------------------------------------------
__device__ __forceinline__ uint32_t smem_u32(const void* p) {
    uint32_t a;
    asm("{ .reg .u64 t; cvta.to.shared.u64 t, %1; cvt.u32.u64 %0, t; }"
        : "=r"(a) : "l"(p));
    return a;
}
__device__ __forceinline__ void cp_async16(uint32_t dst, const void* src) {
    asm volatile("cp.async.cg.shared.global [%0], [%1], 16;"
                 :: "r"(dst), "l"(src));
}
__device__ __forceinline__ void cp_commit() {
    asm volatile("cp.async.commit_group;" ::: "memory");
}
template <int N>
__device__ __forceinline__ void cp_wait() {
    asm volatile("cp.async.wait_group %0;" :: "n"(N) : "memory");
}
__device__ __forceinline__ void mma_f16(float* c, const uint32_t* a,
                                        const uint32_t* b) {
    asm volatile(
        "mma.sync.aligned.m16n8k16.row.col.f32.f16.f16.f32 "
        "{%0,%1,%2,%3}, {%4,%5,%6,%7}, {%8,%9}, {%0,%1,%2,%3};"
        : "+f"(c[0]), "+f"(c[1]), "+f"(c[2]), "+f"(c[3])
        : "r"(a[0]), "r"(a[1]), "r"(a[2]), "r"(a[3]), "r"(b[0]), "r"(b[1]));
}
__device__ __forceinline__ void ldsm_x4(uint32_t& r0, uint32_t& r1,
                                        uint32_t& r2, uint32_t& r3,
                                        uint32_t addr) {
    asm volatile(
        "ldmatrix.sync.aligned.m8n8.x4.shared.b16 {%0,%1,%2,%3}, [%4];"
        : "=r"(r0), "=r"(r1), "=r"(r2), "=r"(r3) : "r"(addr));
}

// ---------------------------------------------------------------------------
// FP16 mma.sync GEMM: C[M,N] = A[M,K] @ Wh[N,K]^T (+bias, epilogue).
// CTA tile 128x128, BK=32 (2 k16-steps), 8 warps (warp tile 64x32),
// 4-stage cp.async pipeline (lookahead 2, single sync per iter).
// Fragment loads via ldmatrix.x4; smem row stride 40 halfs (conflict-free).
// EPI 0: +bias ; EPI 1: gelu(acc+bias) ; EPI 2: (acc+bias+aux)*maskrow
// ---------------------------------------------------------------------------
constexpr int STG_B = 128 * 80;                    // bytes per stage (A or B)
constexpr int G_NSTG = 4;
constexpr int G_SMEM_BYTES = 2 * G_NSTG * STG_B;   // 81920 B

template <int EPI, typename OutT>
__global__ void __launch_bounds__(256, 2)
tc_gemm(const __half* __restrict__ A, int lda,
        const __half* __restrict__ Bh, int ldb,   // Wh[N][K]
        OutT* __restrict__ C, int ldc,
        const float* __restrict__ bias,
        const float* __restrict__ aux, int ldaux,
        const float* __restrict__ mrow,
        int Kk) {
    extern __shared__ char smem[];
    int tid = threadIdx.x, lane = tid & 31, wid = tid >> 5;
    int wm = (wid & 1) * 64, wn = (wid >> 1) * 32;
    int m0 = blockIdx.y * 128, n0 = blockIdx.x * 128;
    int grp = lane >> 2, qid = lane & 3;
    uint32_t sbase = smem_u32(smem);

    // ldmatrix per-lane offsets (halfs), converted to bytes at use.
    // A matrices: mat0=[r0:8,c0:8] mat1=[r8:16,c0:8] mat2=[r0:8,c8:16] mat3=[r8:16,c8:16]
    uint32_t a_lane_off = (uint32_t)(((lane & 15) * 40 + ((lane >> 4) << 3)) * 2);
    // B matrices: mat0=[n0:8,kb:+8] mat1=[n0:8,kb+8:+8] mat2=[n8:16,kb] mat3=[n8:16,kb+8]
    uint32_t b_lane_off = (uint32_t)(((((lane >> 4) << 3) + (lane & 7)) * 40
                                      + (((lane >> 3) & 1) << 3)) * 2);

    float acc[4][4][4];
    #pragma unroll
    for (int a = 0; a < 4; a++)
        #pragma unroll
        for (int b = 0; b < 4; b++)
            #pragma unroll
            for (int c = 0; c < 4; c++) acc[a][b][c] = 0.0f;

    const int KTl = Kk >> 5;

    auto load_tile = [&](int kt, int s) {
        const __half* Ag = A + (size_t)m0 * lda + kt * 32;
        const __half* Bg = Bh + (size_t)n0 * ldb + kt * 32;
        uint32_t abase = sbase + s * STG_B;
        uint32_t bbase = sbase + G_NSTG * STG_B + s * STG_B;
        #pragma unroll
        for (int q = 0; q < 2; q++) {
            int idx = tid + q * 256;
            int row = idx >> 2, seg = idx & 3;   // 4 x 16B per 64B row
            cp_async16(abase + (uint32_t)(row * 80 + seg * 16),
                       Ag + (size_t)row * lda + seg * 8);
            cp_async16(bbase + (uint32_t)(row * 80 + seg * 16),
                       Bg + (size_t)row * ldb + seg * 8);
        }
    };

    // prologue: stages 0,1
    load_tile(0, 0);
    cp_commit();
    if (KTl > 1) load_tile(1, 1);
    cp_commit();

    for (int i = 0; i < KTl; i++) {
        int s = i % G_NSTG;
        {
            int li = i + 2;
            if (li < KTl) load_tile(li, li % G_NSTG);
            cp_commit();
        }
        cp_wait<2>();   // loads of iter i complete
        __syncthreads(); // single barrier per iteration (4 stages, lookahead 2)
        uint32_t abase = sbase + s * STG_B;
        uint32_t bbase = sbase + G_NSTG * STG_B + s * STG_B;
        #pragma unroll
        for (int ks = 0; ks < 2; ks++) {
            int kb = ks * 16;
            uint32_t af[4][4], bf[4][2];
            #pragma unroll
            for (int mi = 0; mi < 4; mi++) {
                uint32_t addr = abase + a_lane_off
                              + (uint32_t)(((wm + mi * 16) * 40 + kb) * 2);
                ldsm_x4(af[mi][0], af[mi][1], af[mi][2], af[mi][3], addr);
            }
            #pragma unroll
            for (int np = 0; np < 2; np++) {
                uint32_t addr = bbase + b_lane_off
                              + (uint32_t)(((wn + np * 16) * 40 + kb) * 2);
                ldsm_x4(bf[2 * np][0], bf[2 * np][1],
                        bf[2 * np + 1][0], bf[2 * np + 1][1], addr);
            }
            #pragma unroll
            for (int mi = 0; mi < 4; mi++)
                #pragma unroll
                for (int ni = 0; ni < 4; ni++)
                    mma_f16(acc[mi][ni], af[mi], bf[ni]);
        }
    }

    __syncthreads();

    // Epilogue
    #pragma unroll
    for (int mi = 0; mi < 4; mi++) {
        #pragma unroll
        for (int rr = 0; rr < 2; rr++) {
            int row = m0 + wm + mi * 16 + grp + rr * 8;
            float mval = 1.0f;
            if (EPI == 2) mval = mrow[row];
            #pragma unroll
            for (int ni = 0; ni < 4; ni++) {
                int col = n0 + wn + ni * 8 + 2 * qid;
                float x0 = acc[mi][ni][rr * 2 + 0] + bias[col];
                float x1 = acc[mi][ni][rr * 2 + 1] + bias[col + 1];
                if (EPI == 1) {
                    x0 = 0.5f * x0 * (1.0f + erff(x0 * 0.70710678118654752f));
                    x1 = 0.5f * x1 * (1.0f + erff(x1 * 0.70710678118654752f));
                }
                if (EPI == 2) {
                    float2 av = *(const float2*)(aux + (size_t)row * ldaux + col);
                    x0 = (x0 + av.x) * mval;
                    x1 = (x1 + av.y) * mval;
                }
                if constexpr (sizeof(OutT) == 2) {
                    *(__half2*)((__half*)C + (size_t)row * ldc + col) =
                        __floats2half2_rn(x0, x1);
                } else {
                    *(float2*)((float*)C + (size_t)row * ldc + col) =
                        make_float2(x0, x1);
                }
            }
        }
    }
}

// ---------------------------------------------------------------------------
// Weight prep: dst[N][K] = (half) src[K][N]. Tile 64(K) x 32(N).
// ---------------------------------------------------------------------------
__global__ void __launch_bounds__(256)
wprep_kernel(const float* __restrict__ src, __half* __restrict__ dst,
             int K, int N) {
    __shared__ float tile[64][33];
    int kb = blockIdx.y * 64, nb = blockIdx.x * 32;
    int tid = threadIdx.x;
    #pragma unroll
    for (int q = 0; q < 8; q++) {
        int idx = tid + q * 256;
        int row = idx >> 5, col = idx & 31;
        tile[row][col] = src[(size_t)(kb + row) * N + nb + col];
    }
    __syncthreads();
    #pragma unroll
    for (int q = 0; q < 4; q++) {
        int idx = tid + q * 256;
        int n = idx >> 5, kk = idx & 31;
        __half2 hv = __floats2half2_rn(tile[2 * kk][n], tile[2 * kk + 1][n]);
        *(__half2*)(dst + (size_t)(nb + n) * K + kb + 2 * kk) = hv;
    }
}

// ---------------------------------------------------------------------------
// LayerNorm: block per row, 256 threads, half output.
// ---------------------------------------------------------------------------
__global__ void layernorm_kernel(const float* __restrict__ x,
                                 const float* __restrict__ g,
                                 const float* __restrict__ bta,
                                 __half* __restrict__ y) {
    int row = blockIdx.x;
    int tid = threadIdx.x;
    float4 v = ((const float4*)(x + (size_t)row * D))[tid];
    float s = v.x + v.y + v.z + v.w;
    float sq = v.x * v.x + v.y * v.y + v.z * v.z + v.w * v.w;
    __shared__ float ss[256], sv[256];
    ss[tid] = s; sv[tid] = sq;
    __syncthreads();
    #pragma unroll
    for (int o = 128; o; o >>= 1) {
        if (tid < o) { ss[tid] += ss[tid + o]; sv[tid] += sv[tid + o]; }
        __syncthreads();
    }
    float mu = ss[0] * (1.0f / D);
    float var = sv[0] * (1.0f / D) - mu * mu;
    float rstd = rsqrtf(var + 1e-5f);
    int c = tid * 4;
    float4 gv = *(const float4*)(g + c);
    float4 bv = *(const float4*)(bta + c);
    __half2 ha = __floats2half2_rn((v.x - mu) * rstd * gv.x + bv.x,
                                   (v.y - mu) * rstd * gv.y + bv.y);
    __half2 hb = __floats2half2_rn((v.z - mu) * rstd * gv.z + bv.z,
                                   (v.w - mu) * rstd * gv.w + bv.w);
    uint2 st;
    st.x = *(uint32_t*)&ha;
    st.y = *(uint32_t*)&hb;
    *(uint2*)(y + (size_t)row * D + c) = st;
}

// ---------------------------------------------------------------------------
// Causal depthwise conv over time, half2-vectorized over channels.
// ---------------------------------------------------------------------------
template <int KW>
__global__ void dwconv_kernel(const __half* __restrict__ x,
                              const float* __restrict__ w,
                              const float* __restrict__ bias,
                              __half* __restrict__ y /* pre-offset, stride 3D */) {
    int idx = blockIdx.x * blockDim.x + threadIdx.x;  // over M*D/2
    int d2 = idx & (D / 2 - 1);
    int d = d2 * 2;
    int bt = idx >> 9;
    int t = bt & (T - 1);
    float a0 = bias[d], a1 = bias[d + 1];
    #pragma unroll
    for (int j = 0; j < KW; j++) {
        int tt = t - (KW - 1) + j;
        if (tt >= 0) {
            __half2 xv = *(const __half2*)(x + ((size_t)(bt - (KW - 1) + j)) * D + d);
            float2 xf = __half22float2(xv);
            a0 += w[d * KW + j] * xf.x;
            a1 += w[(d + 1) * KW + j] * xf.y;
        }
    }
    *(__half2*)(y + (size_t)bt * (3 * D) + d) = __floats2half2_rn(a0, a1);
}

// ---------------------------------------------------------------------------
// Linear attention, chunked (pass1 -> prefix scan -> parallel pass2).
// ---------------------------------------------------------------------------
__device__ __forceinline__ float elu1(float x) {
    return x > 0.0f ? x + 1.0f : expf(x);
}

__global__ void __launch_bounds__(1024)
attn_pass1(const float* __restrict__ proj, const float* __restrict__ mask,
           float* __restrict__ state) {
    int bh = blockIdx.x / NC, c = blockIdx.x % NC;
    int b = bh / H, h = bh % H;
    int d = threadIdx.x, e = threadIdx.y;
    int tid = e * 32 + d;
    __shared__ float ks[CHUNK][32];
    __shared__ float vs[CHUNK][32];
    int t0 = c * CHUNK;
    for (int i = tid; i < CHUNK * 32; i += 1024) {
        int t = i >> 5, dd = i & 31;
        int rowg = b * T + t0 + t;
        size_t base = (size_t)rowg * NPROJ;
        float m = mask[rowg];
        float kv = proj[base + 1536 + h * 32 + dd];
        ks[t][dd] = elu1(kv) * m;
        vs[t][dd] = proj[base + 2048 + h * 32 + dd] * m;
    }
    __syncthreads();
    float S = 0.0f, kp = 0.0f;
    #pragma unroll 4
    for (int t = 0; t < CHUNK; t++) {
        float kd = ks[t][d];
        S += kd * vs[t][e];
        kp += kd;
    }
    float* st = state + (size_t)blockIdx.x * STATE_STRIDE;
    st[e * 32 + d] = S;
    if (e == 0) st[1024 + d] = kp;
}

// Exclusive prefix over chunks, 8-way sliced for latency hiding.
__global__ void scan_state(const float* __restrict__ st,
                           float* __restrict__ st2) {
    int bh = blockIdx.x;                       // 32
    int i = blockIdx.y * 132 + threadIdx.x;    // 8 slices x 132
    if (i >= STATE_STRIDE) return;
    float acc = 0.0f;
    for (int c = 0; c < NC; c++) {
        size_t idx = ((size_t)(bh * NC + c)) * STATE_STRIDE + i;
        st2[idx] = acc;
        acc += st[idx];
    }
}

__global__ void __launch_bounds__(256)
attn_pass2(const float* __restrict__ proj, const float* __restrict__ mask,
           const float* __restrict__ st2, __half* __restrict__ outa) {
    int bh = blockIdx.x / NC, c = blockIdx.x % NC;
    int b = bh / H, h = bh % H;
    int tid = threadIdx.x;
    __shared__ float qs[CHUNK][36];
    __shared__ float ks[CHUNK][36];
    __shared__ float vs[CHUNK][33];
    __shared__ float Aa[CHUNK][CHUNK];
    __shared__ float Ps[32][33];
    __shared__ float kpp[32];
    __shared__ float ms[CHUNK];
    int t0 = c * CHUNK;

    for (int i = tid; i < CHUNK * 32; i += 256) {
        int t = i >> 5, dd = i & 31;
        int rowg = b * T + t0 + t;
        size_t base = (size_t)rowg * NPROJ;
        float m = mask[rowg];
        qs[t][dd] = elu1(proj[base + 1024 + h * 32 + dd]) * m;
        ks[t][dd] = elu1(proj[base + 1536 + h * 32 + dd]) * m;
        vs[t][dd] = proj[base + 2048 + h * 32 + dd] * m;
        if (dd == 0) ms[t] = m;
    }
    const float* stp = st2 + (size_t)blockIdx.x * STATE_STRIDE;
    for (int i = tid; i < 1024; i += 256) {
        int d = i & 31, e = i >> 5;
        Ps[d][e] = stp[i];
    }
    if (tid < 32) kpp[tid] = stp[1024 + tid];
    __syncthreads();

    // A[t][tp] = q[t] . k[tp]
    {
        int ty = tid >> 4, tx = tid & 15;
        int r0 = ty * 4, c0 = tx * 4;
        float a4[4][4] = {};
        #pragma unroll
        for (int d0 = 0; d0 < 32; d0 += 4) {
            float4 qr[4], kr[4];
            #pragma unroll
            for (int i = 0; i < 4; i++)
                qr[i] = *(const float4*)&qs[r0 + i][d0];
            #pragma unroll
            for (int j = 0; j < 4; j++)
                kr[j] = *(const float4*)&ks[c0 + j][d0];
            #pragma unroll
            for (int i = 0; i < 4; i++)
                #pragma unroll
                for (int j = 0; j < 4; j++)
                    a4[i][j] += qr[i].x * kr[j].x + qr[i].y * kr[j].y
                              + qr[i].z * kr[j].z + qr[i].w * kr[j].w;
        }
        #pragma unroll
        for (int i = 0; i < 4; i++)
            #pragma unroll
            for (int j = 0; j < 4; j++)
                Aa[r0 + i][c0 + j] = a4[i][j];
    }
    __syncthreads();

    int w = tid >> 5, e = tid & 31;
    #pragma unroll
    for (int ii = 0; ii < 8; ii++) {
        int t = w + 8 * ii;
        float num = 0.0f, den = 0.0f;
        #pragma unroll
        for (int d = 0; d < 32; d++) {
            float qd = qs[t][d];
            num += qd * Ps[d][e];
            den += qd * kpp[d];
        }
        const float* Arow = Aa[t];
        for (int tp = 0; tp <= t; tp++) {
            float a = Arow[tp];
            num += a * vs[tp][e];
            den += a;
        }
        outa[(size_t)(b * T + t0 + t) * INNER + h * 32 + e] =
            __float2half(num / (den + 1e-6f) * ms[t]);
    }
}

// ---------------------------------------------------------------------------
// Fused gate + LN2
// ---------------------------------------------------------------------------
__global__ void gate_ln2(const float* __restrict__ inp,
                         const float* __restrict__ proj,
                         const float* __restrict__ mixed,
                         const float* __restrict__ mask,
                         const float* __restrict__ g,
                         const float* __restrict__ bta,
                         float* __restrict__ out1,
                         __half* __restrict__ hb) {
    int row = blockIdx.x;
    int tid = threadIdx.x;
    int c = tid * 4;
    float mk = mask[row];
    float4 iv = ((const float4*)(inp + (size_t)row * D))[tid];
    float4 mv = ((const float4*)(mixed + (size_t)row * D))[tid];
    float4 gt = *(const float4*)(proj + (size_t)row * NPROJ + c);
    float4 o;
    o.x = (iv.x + mv.x / (1.0f + expf(-gt.x))) * mk;
    o.y = (iv.y + mv.y / (1.0f + expf(-gt.y))) * mk;
    o.z = (iv.z + mv.z / (1.0f + expf(-gt.z))) * mk;
    o.w = (iv.w + mv.w / (1.0f + expf(-gt.w))) * mk;
    ((float4*)(out1 + (size_t)row * D))[tid] = o;

    float s = o.x + o.y + o.z + o.w;
    float sq = o.x * o.x + o.y * o.y + o.z * o.z + o.w * o.w;
    __shared__ float ss[256], sv[256];
    ss[tid] = s; sv[tid] = sq;
    __syncthreads();
    #pragma unroll
    for (int of = 128; of; of >>= 1) {
        if (tid < of) { ss[tid] += ss[tid + of]; sv[tid] += sv[tid + of]; }
        __syncthreads();
    }
    float mu = ss[0] * (1.0f / D);
    float var = sv[0] * (1.0f / D) - mu * mu;
    float rstd = rsqrtf(var + 1e-5f);
    float4 gv = *(const float4*)(g + c);
    float4 bv = *(const float4*)(bta + c);
    __half2 ha = __floats2half2_rn((o.x - mu) * rstd * gv.x + bv.x,
                                   (o.y - mu) * rstd * gv.y + bv.y);
    __half2 hb2 = __floats2half2_rn((o.z - mu) * rstd * gv.z + bv.z,
                                    (o.w - mu) * rstd * gv.w + bv.w);
    uint2 st;
    st.x = *(uint32_t*)&ha;
    st.y = *(uint32_t*)&hb2;
    *(uint2*)(hb + (size_t)row * D + c) = st;
}

// ---------------------------------------------------------------------------
// Launch
// ---------------------------------------------------------------------------
extern "C" void kernel_launch(void* const* d_in, const int* in_sizes, int n_in,
                              void* d_out, int out_size) {
    const float* inputs = (const float*)d_in[0];
    const float* mask   = (const float*)d_in[1];
    const float* ln1_g  = (const float*)d_in[2];
    const float* ln1_b  = (const float*)d_in[3];
    const float* W_in   = (const float*)d_in[4];
    const float* b_in   = (const float*)d_in[5];
    const float* W_c    = (const float*)d_in[6];
    const float* b_c    = (const float*)d_in[7];
    const float* w_t    = (const float*)d_in[8];
    const float* b_t    = (const float*)d_in[9];
    const float* w_p    = (const float*)d_in[10];
    const float* b_p    = (const float*)d_in[11];
    const float* W_mix  = (const float*)d_in[12];
    const float* b_mix  = (const float*)d_in[13];
    const float* ln2_g  = (const float*)d_in[14];
    const float* ln2_b  = (const float*)d_in[15];
    const float* W1     = (const float*)d_in[16];
    const float* b1     = (const float*)d_in[17];
    const float* W2     = (const float*)d_in[18];
    const float* b2     = (const float*)d_in[19];
    float* out = (float*)d_out;

    float *proj, *mixed, *out1, *state, *state2;
    __half *normedh, *attnh, *cath, *hh, *ffn1h;
    __half *win, *wc, *wmix, *w1, *w2;
    cudaGetSymbolAddress((void**)&proj,   g_proj);
    cudaGetSymbolAddress((void**)&mixed,  g_mixed);
    cudaGetSymbolAddress((void**)&out1,   g_out1);
    cudaGetSymbolAddress((void**)&state,  g_state);
    cudaGetSymbolAddress((void**)&state2, g_state2);
    cudaGetSymbolAddress((void**)&normedh, h_normed);
    cudaGetSymbolAddress((void**)&attnh,   h_attn);
    cudaGetSymbolAddress((void**)&cath,    h_cat);
    cudaGetSymbolAddress((void**)&hh,      h_h);
    cudaGetSymbolAddress((void**)&ffn1h,   h_ffn1);
    cudaGetSymbolAddress((void**)&win,  wh_in);
    cudaGetSymbolAddress((void**)&wc,   wh_c);
    cudaGetSymbolAddress((void**)&wmix, wh_mix);
    cudaGetSymbolAddress((void**)&w1,   wh_1);
    cudaGetSymbolAddress((void**)&w2,   wh_2);

    // Raise dynamic smem limit for the 4-stage GEMM (81920 B > 48 KB default).
    cudaFuncSetAttribute(tc_gemm<0, float>,
                         cudaFuncAttributeMaxDynamicSharedMemorySize, G_SMEM_BYTES);
    cudaFuncSetAttribute(tc_gemm<0, __half>,
                         cudaFuncAttributeMaxDynamicSharedMemorySize, G_SMEM_BYTES);
    cudaFuncSetAttribute(tc_gemm<1, __half>,
                         cudaFuncAttributeMaxDynamicSharedMemorySize, G_SMEM_BYTES);
    cudaFuncSetAttribute(tc_gemm<2, float>,
                         cudaFuncAttributeMaxDynamicSharedMemorySize, G_SMEM_BYTES);

    // Weight prep (transpose + fp16)
    wprep_kernel<<<dim3(NPROJ / 32, D / 64), 256>>>(W_in, win, D, NPROJ);
    wprep_kernel<<<dim3(D / 32, INNER / 64), 256>>>(W_c, wc, INNER, D);
    wprep_kernel<<<dim3(D / 32, (3 * D) / 64), 256>>>(W_mix, wmix, 3 * D, D);
    wprep_kernel<<<dim3(FF / 32, D / 64), 256>>>(W1, w1, D, FF);
    wprep_kernel<<<dim3(D / 32, FF / 64), 256>>>(W2, w2, FF, D);

    // 1. LN1 -> half
    layernorm_kernel<<<M, 256>>>(inputs, ln1_g, ln1_b, normedh);

    // 2. proj = normed @ W_in + b_in (fp32 out)
    tc_gemm<0, float><<<dim3(NPROJ / 128, M / 128), 256, G_SMEM_BYTES>>>(
        normedh, D, win, D, proj, NPROJ, b_in, nullptr, 0, nullptr, D);

    // 3. linear attention
    attn_pass1<<<B * H * NC, dim3(32, 32)>>>(proj, mask, state);
    scan_state<<<dim3(B * H, 8), 132>>>(state, state2);
    attn_pass2<<<B * H * NC, 256>>>(proj, mask, state2, attnh);

    // 4. content = attn @ W_c + b_c -> cat[:, 0:D] (half)
    tc_gemm<0, __half><<<dim3(D / 128, M / 128), 256, G_SMEM_BYTES>>>(
        attnh, INNER, wc, INNER, cath, 3 * D, b_c, nullptr, 0, nullptr, INNER);

    // 5. dwconvs -> cat[:, D:2D] and cat[:, 2D:3D]
    dwconv_kernel<KT><<<(M * D / 2) / 256, 256>>>(normedh, w_t, b_t, cath + D);
    dwconv_kernel<KP><<<(M * D / 2) / 256, 256>>>(normedh, w_p, b_p, cath + 2 * D);

    // 6. mixed = cat @ W_mix + b_mix (fp32 out)
    tc_gemm<0, float><<<dim3(D / 128, M / 128), 256, G_SMEM_BYTES>>>(
        cath, 3 * D, wmix, 3 * D, mixed, D, b_mix, nullptr, 0, nullptr, 3 * D);

    // 7+8. fused gate + LN2
    gate_ln2<<<M, 256>>>(inputs, proj, mixed, mask, ln2_g, ln2_b, out1, hh);

    // 9. ffn1 = gelu(h @ W1 + b1) (half out)
    tc_gemm<1, __half><<<dim3(FF / 128, M / 128), 256, G_SMEM_BYTES>>>(
        hh, D, w1, D, ffn1h, FF, b1, nullptr, 0, nullptr, D);

    // 10. out = (out1 + ffn1 @ W2 + b2) * mask (fp32 out)
    tc_gemm<2, float><<<dim3(D / 128, M / 128), 256, G_SMEM_BYTES>>>(
        ffn1h, FF, w2, FF, out, D, b2, out1, D, mask, FF);
}